// round 3
// baseline (speedup 1.0000x reference)
#include <cuda_runtime.h>
#include <cuda_bf16.h>
#include <cstdint>

#define N_NODES 50000
#define N_EDGES 800000
#define CH 128

#define SCAN_BLK 512
#define NSCAN_BLOCKS ((N_NODES + SCAN_BLK - 1) / SCAN_BLK)  // 98

// ---------------- device scratch (no allocations allowed) ----------------
__device__ int   g_is64;
__device__ int   g_deg[N_NODES];
__device__ int   g_rowptr[N_NODES + 1];
__device__ int   g_cursor[N_NODES];
__device__ int   g_csr[N_EDGES];
__device__ int   g_bsum[NSCAN_BLOCKS];
__device__ int   g_boff[NSCAN_BLOCKS];
__device__ float g_invdeg[N_NODES];
__device__ float g_bufA[(size_t)N_NODES * CH];
__device__ float g_bufB[(size_t)N_NODES * CH];
__device__ float g_agg [(size_t)N_NODES * CH];

// ---------------- packed f32x2 helpers ----------------
__device__ __forceinline__ void ffma2(unsigned long long& d, unsigned long long a,
                                      unsigned long long b) {
    asm("fma.rn.f32x2 %0, %1, %2, %0;" : "+l"(d) : "l"(a), "l"(b));
}
__device__ __forceinline__ unsigned long long pack2(float x) {
    unsigned long long r;
    asm("mov.b64 %0, {%1, %1};" : "=l"(r) : "f"(x));
    return r;
}
__device__ __forceinline__ float2 unpack2(unsigned long long v) {
    float2 f;
    asm("mov.b64 {%0, %1}, %2;" : "=f"(f.x), "=f"(f.y) : "l"(v));
    return f;
}

// ---------------- small setup kernels ----------------
__global__ void zero_init_kernel() {
    int i = blockIdx.x * blockDim.x + threadIdx.x;
    if (i < N_NODES) g_deg[i] = 0;
}

// Detect whether edge_index is int64 or int32 on disk.
// If int64 (little endian, values in [0,50000)), every odd 32-bit word is 0.
__global__ void detect_kernel(const unsigned* __restrict__ w) {
    __shared__ int any32;
    if (threadIdx.x == 0) any32 = 0;
    __syncthreads();
    for (int i = threadIdx.x; i < 1024; i += blockDim.x) {
        if (w[2 * i + 1] != 0u) any32 = 1;  // benign race
    }
    __syncthreads();
    if (threadIdx.x == 0) g_is64 = any32 ? 0 : 1;
}

__device__ __forceinline__ int load_edge(const void* ei, int idx, int is64) {
    if (is64) return (int)((const long long*)ei)[idx];
    return ((const int*)ei)[idx];
}

__global__ void deg_kernel(const void* __restrict__ ei) {
    int e = blockIdx.x * blockDim.x + threadIdx.x;
    if (e >= N_EDGES) return;
    int is64 = g_is64;
    int d = load_edge(ei, N_EDGES + e, is64);
    atomicAdd(&g_deg[d], 1);
}

// ---------------- 3-phase multi-block exclusive scan ----------------
__global__ void bsum_kernel() {
    int i = blockIdx.x * SCAN_BLK + threadIdx.x;
    int v = (i < N_NODES) ? g_deg[i] : 0;
    int lane = threadIdx.x & 31, wid = threadIdx.x >> 5;
    __shared__ int ws[SCAN_BLK / 32];
#pragma unroll
    for (int off = 16; off > 0; off >>= 1)
        v += __shfl_down_sync(0xFFFFFFFFu, v, off);
    if (lane == 0) ws[wid] = v;
    __syncthreads();
    if (wid == 0) {
        v = (lane < SCAN_BLK / 32) ? ws[lane] : 0;
#pragma unroll
        for (int off = 16; off > 0; off >>= 1)
            v += __shfl_down_sync(0xFFFFFFFFu, v, off);
        if (lane == 0) g_bsum[blockIdx.x] = v;
    }
}

__global__ void bscan_kernel() {  // 1 block, 128 threads (NSCAN_BLOCKS=98)
    __shared__ int s[128];
    int t = threadIdx.x;
    int v = (t < NSCAN_BLOCKS) ? g_bsum[t] : 0;
    s[t] = v;
    __syncthreads();
    for (int off = 1; off < 128; off <<= 1) {
        int u = 0;
        if (t >= off) u = s[t - off];
        __syncthreads();
        if (t >= off) s[t] += u;
        __syncthreads();
    }
    if (t < NSCAN_BLOCKS) g_boff[t] = s[t] - v;  // exclusive
    if (t == NSCAN_BLOCKS - 1) g_rowptr[N_NODES] = s[t];
}

__global__ void scatter_scan_kernel() {
    int i = blockIdx.x * SCAN_BLK + threadIdx.x;
    int lane = threadIdx.x & 31, wid = threadIdx.x >> 5;
    int d = (i < N_NODES) ? g_deg[i] : 0;
    // warp inclusive scan
    int incl = d;
#pragma unroll
    for (int off = 1; off < 32; off <<= 1) {
        int u = __shfl_up_sync(0xFFFFFFFFu, incl, off);
        if (lane >= off) incl += u;
    }
    __shared__ int wsum[SCAN_BLK / 32];
    __shared__ int wexcl[SCAN_BLK / 32];
    if (lane == 31) wsum[wid] = incl;
    __syncthreads();
    if (threadIdx.x == 0) {
        int run = 0;
#pragma unroll
        for (int w = 0; w < SCAN_BLK / 32; w++) { wexcl[w] = run; run += wsum[w]; }
    }
    __syncthreads();
    if (i < N_NODES) {
        int ex = incl - d + wexcl[wid] + g_boff[blockIdx.x];
        g_rowptr[i] = ex;
        g_cursor[i] = ex;
        g_invdeg[i] = (d > 0) ? (1.0f / (float)d) : 0.0f;
    }
}

__global__ void fill_kernel(const void* __restrict__ ei) {
    int e = blockIdx.x * blockDim.x + threadIdx.x;
    if (e >= N_EDGES) return;
    int is64 = g_is64;
    int s = load_edge(ei, e, is64);
    int d = load_edge(ei, N_EDGES + e, is64);
    int pos = atomicAdd(&g_cursor[d], 1);
    g_csr[pos] = s;
}

// ---------------- aggregation: one warp per node, gather over CSR ----------------
// 4-way unrolled with independent accumulators for MLP>=4.
__global__ void agg_kernel(const float* __restrict__ H, float* __restrict__ Agg) {
    int gt = blockIdx.x * blockDim.x + threadIdx.x;
    int node = gt >> 5;
    int lane = gt & 31;
    if (node >= N_NODES) return;
    int beg = g_rowptr[node];
    int end = g_rowptr[node + 1];
    float4 acc0 = make_float4(0.f, 0.f, 0.f, 0.f);
    float4 acc1 = acc0, acc2 = acc0, acc3 = acc0;
    int i = beg;
    for (; i + 4 <= end; i += 4) {
        int s0 = __ldg(&g_csr[i + 0]);
        int s1 = __ldg(&g_csr[i + 1]);
        int s2 = __ldg(&g_csr[i + 2]);
        int s3 = __ldg(&g_csr[i + 3]);
        float4 v0 = *(const float4*)(H + (size_t)s0 * CH + lane * 4);
        float4 v1 = *(const float4*)(H + (size_t)s1 * CH + lane * 4);
        float4 v2 = *(const float4*)(H + (size_t)s2 * CH + lane * 4);
        float4 v3 = *(const float4*)(H + (size_t)s3 * CH + lane * 4);
        acc0.x += v0.x; acc0.y += v0.y; acc0.z += v0.z; acc0.w += v0.w;
        acc1.x += v1.x; acc1.y += v1.y; acc1.z += v1.z; acc1.w += v1.w;
        acc2.x += v2.x; acc2.y += v2.y; acc2.z += v2.z; acc2.w += v2.w;
        acc3.x += v3.x; acc3.y += v3.y; acc3.z += v3.z; acc3.w += v3.w;
    }
    for (; i < end; i++) {
        int s0 = __ldg(&g_csr[i]);
        float4 v0 = *(const float4*)(H + (size_t)s0 * CH + lane * 4);
        acc0.x += v0.x; acc0.y += v0.y; acc0.z += v0.z; acc0.w += v0.w;
    }
    acc0.x += acc1.x + acc2.x + acc3.x;
    acc0.y += acc1.y + acc2.y + acc3.y;
    acc0.z += acc1.z + acc2.z + acc3.z;
    acc0.w += acc1.w + acc2.w + acc3.w;
    float s = g_invdeg[node];
    acc0.x *= s; acc0.y *= s; acc0.z *= s; acc0.w *= s;
    *(float4*)(Agg + (size_t)node * CH + lane * 4) = acc0;
}

// ---------------- fused dual GEMM: Out = relu(Agg@Wl + bl + H@Wr) ----------------
// 256 threads; each thread: 8 rows x 8 cols (two separated float4 col groups at
// tx*4 and 64+tx*4 -> conflict-free 16B-stride W loads). Packed fma.rn.f32x2.
#define GEMM_THREADS 256
#define GEMM_BM 128
#define GEMM_KC 32
#define GEMM_SMEM_BYTES ((2 * 128 * 128 + 2 * GEMM_BM * GEMM_KC) * 4)  // 160 KB

__global__ void __launch_bounds__(GEMM_THREADS, 1)
gemm_kernel(const float* __restrict__ Agg, const float* __restrict__ H,
            const float* __restrict__ Wl, const float* __restrict__ Wr,
            const float* __restrict__ bl, float* __restrict__ Out) {
    extern __shared__ float smem[];
    float* sWl = smem;                  // 128x128
    float* sWr = smem + 16384;          // 128x128
    float* sA  = smem + 32768;          // BM x KC
    float* sH  = sA + GEMM_BM * GEMM_KC;

    int tid = threadIdx.x;
    int row0 = blockIdx.x * GEMM_BM;
    int tx = tid & 15;   // col group: cols [tx*4, tx*4+4) and [64+tx*4, 64+tx*4+4)
    int ty = tid >> 4;   // row group: rows ty*8 .. ty*8+7

    // stage weights (4096 float4 each)
    for (int i = tid; i < 4096; i += GEMM_THREADS) {
        ((float4*)sWl)[i] = ((const float4*)Wl)[i];
        ((float4*)sWr)[i] = ((const float4*)Wr)[i];
    }

    unsigned long long acc[8][4];
#pragma unroll
    for (int r = 0; r < 8; r++)
#pragma unroll
        for (int c = 0; c < 4; c++) acc[r][c] = 0ull;

    for (int kc = 0; kc < 128; kc += GEMM_KC) {
        __syncthreads();  // protect sA/sH (also orders W-load on first iter)
        // load A/H chunk: BM rows x KC cols = 1024 float4 each
        for (int i = tid; i < 1024; i += GEMM_THREADS) {
            int r   = i >> 3;        // 8 float4 per row
            int kk4 = i & 7;
            int row = row0 + r;
            float4 va = make_float4(0.f, 0.f, 0.f, 0.f);
            float4 vh = va;
            if (row < N_NODES) {
                va = *(const float4*)(Agg + (size_t)row * CH + kc + kk4 * 4);
                vh = *(const float4*)(H   + (size_t)row * CH + kc + kk4 * 4);
            }
            ((float4*)sA)[i] = va;
            ((float4*)sH)[i] = vh;
        }
        __syncthreads();
#pragma unroll
        for (int kk = 0; kk < GEMM_KC; kk += 4) {
            // stage 4 k-steps of A/H for this thread's 8 rows (broadcast LDS.128)
            float a4[8][4], h4[8][4];
#pragma unroll
            for (int r = 0; r < 8; r++) {
                *(float4*)a4[r] = *(const float4*)(sA + (ty * 8 + r) * GEMM_KC + kk);
                *(float4*)h4[r] = *(const float4*)(sH + (ty * 8 + r) * GEMM_KC + kk);
            }
#pragma unroll
            for (int j = 0; j < 4; j++) {
                const float* wlrow = sWl + (kc + kk + j) * 128;
                const float* wrrow = sWr + (kc + kk + j) * 128;
                ulonglong2 wla = *(const ulonglong2*)(wlrow + tx * 4);
                ulonglong2 wlb = *(const ulonglong2*)(wlrow + 64 + tx * 4);
                ulonglong2 wra = *(const ulonglong2*)(wrrow + tx * 4);
                ulonglong2 wrb = *(const ulonglong2*)(wrrow + 64 + tx * 4);
#pragma unroll
                for (int r = 0; r < 8; r++) {
                    unsigned long long a = pack2(a4[r][j]);
                    unsigned long long h = pack2(h4[r][j]);
                    ffma2(acc[r][0], a, wla.x);
                    ffma2(acc[r][1], a, wla.y);
                    ffma2(acc[r][2], a, wlb.x);
                    ffma2(acc[r][3], a, wlb.y);
                    ffma2(acc[r][0], h, wra.x);
                    ffma2(acc[r][1], h, wra.y);
                    ffma2(acc[r][2], h, wrb.x);
                    ffma2(acc[r][3], h, wrb.y);
                }
            }
        }
    }

    float4 b0 = *(const float4*)(bl + tx * 4);
    float4 b1 = *(const float4*)(bl + 64 + tx * 4);
#pragma unroll
    for (int r = 0; r < 8; r++) {
        int row = row0 + ty * 8 + r;
        if (row < N_NODES) {
            float2 p0 = unpack2(acc[r][0]);
            float2 p1 = unpack2(acc[r][1]);
            float2 p2 = unpack2(acc[r][2]);
            float2 p3 = unpack2(acc[r][3]);
            float4 o0, o1;
            o0.x = fmaxf(p0.x + b0.x, 0.f);
            o0.y = fmaxf(p0.y + b0.y, 0.f);
            o0.z = fmaxf(p1.x + b0.z, 0.f);
            o0.w = fmaxf(p1.y + b0.w, 0.f);
            o1.x = fmaxf(p2.x + b1.x, 0.f);
            o1.y = fmaxf(p2.y + b1.y, 0.f);
            o1.z = fmaxf(p3.x + b1.z, 0.f);
            o1.w = fmaxf(p3.y + b1.w, 0.f);
            *(float4*)(Out + (size_t)row * CH + tx * 4) = o0;
            *(float4*)(Out + (size_t)row * CH + 64 + tx * 4) = o1;
        }
    }
}

// ---------------- head: logits = H @ Wh + bh, one warp per node ----------------
__global__ void head_kernel(const float* __restrict__ H, const float* __restrict__ Wh,
                            const float* __restrict__ bh, float* __restrict__ out) {
    __shared__ float sWh[CH];
    if (threadIdx.x < CH) sWh[threadIdx.x] = Wh[threadIdx.x];
    __syncthreads();
    int gt = blockIdx.x * blockDim.x + threadIdx.x;
    int node = gt >> 5;
    int lane = gt & 31;
    if (node >= N_NODES) return;
    float4 h = *(const float4*)(H + (size_t)node * CH + lane * 4);
    float4 w = *(const float4*)(sWh + lane * 4);
    float s = h.x * w.x + h.y * w.y + h.z * w.z + h.w * w.w;
#pragma unroll
    for (int off = 16; off > 0; off >>= 1)
        s += __shfl_down_sync(0xFFFFFFFFu, s, off);
    if (lane == 0) out[node] = s + bh[0];
}

// ---------------- launch ----------------
extern "C" void kernel_launch(void* const* d_in, const int* in_sizes, int n_in,
                              void* d_out, int out_size) {
    const float* x  = (const float*)d_in[0];
    const void*  ei = d_in[1];
    const float* Wl[3] = {(const float*)d_in[2], (const float*)d_in[5], (const float*)d_in[8]};
    const float* Wr[3] = {(const float*)d_in[3], (const float*)d_in[6], (const float*)d_in[9]};
    const float* bl[3] = {(const float*)d_in[4], (const float*)d_in[7], (const float*)d_in[10]};
    const float* Wh = (const float*)d_in[11];
    const float* bh = (const float*)d_in[12];
    float* out = (float*)d_out;

    cudaFuncSetAttribute(gemm_kernel, cudaFuncAttributeMaxDynamicSharedMemorySize,
                         GEMM_SMEM_BYTES);

    void *pA, *pB, *pAgg;
    cudaGetSymbolAddress(&pA, g_bufA);
    cudaGetSymbolAddress(&pB, g_bufB);
    cudaGetSymbolAddress(&pAgg, g_agg);
    float* bufA = (float*)pA;
    float* bufB = (float*)pB;
    float* agg  = (float*)pAgg;

    // CSR build
    zero_init_kernel<<<(N_NODES + 255) / 256, 256>>>();
    detect_kernel<<<1, 256>>>((const unsigned*)ei);
    deg_kernel<<<(N_EDGES + 255) / 256, 256>>>(ei);
    bsum_kernel<<<NSCAN_BLOCKS, SCAN_BLK>>>();
    bscan_kernel<<<1, 128>>>();
    scatter_scan_kernel<<<NSCAN_BLOCKS, SCAN_BLK>>>();
    fill_kernel<<<(N_EDGES + 255) / 256, 256>>>(ei);

    const int warp_grid = (N_NODES * 32 + 255) / 256;
    const int gemm_grid = (N_NODES + GEMM_BM - 1) / GEMM_BM;

    const float* Hin = x;
    float* layer_out[3] = {bufA, bufB, bufA};
    for (int l = 0; l < 3; l++) {
        agg_kernel<<<warp_grid, 256>>>(Hin, agg);
        gemm_kernel<<<gemm_grid, GEMM_THREADS, GEMM_SMEM_BYTES>>>(
            agg, Hin, Wl[l], Wr[l], bl[l], layer_out[l]);
        Hin = layer_out[l];
    }
    head_kernel<<<warp_grid, 256>>>(Hin, Wh, bh, out);
}

// round 5
// speedup vs baseline: 1.4360x; 1.4360x over previous
#include <cuda_runtime.h>
#include <cuda_bf16.h>
#include <cstdint>

#define N_NODES 50000
#define N_EDGES 800000
#define CH 128

#define SCAN_BLK 512
#define NSCAN_BLOCKS ((N_NODES + SCAN_BLK - 1) / SCAN_BLK)  // 98

// ---------------- device scratch (no allocations allowed) ----------------
__device__ int   g_is64;
__device__ int   g_deg[N_NODES];
__device__ int   g_rowptr[N_NODES + 1];
__device__ int   g_cursor[N_NODES];
__device__ int   g_csr[N_EDGES];
__device__ int   g_bsum[NSCAN_BLOCKS];
__device__ int   g_boff[NSCAN_BLOCKS];
__device__ float g_invdeg[N_NODES];
__device__ float g_bufA[(size_t)N_NODES * CH];   // fp32 H ping
__device__ float g_bufB[(size_t)N_NODES * CH];   // fp32 H pong
__device__ __nv_bfloat16 g_xHi[(size_t)N_NODES * CH];
__device__ __nv_bfloat16 g_xLo[(size_t)N_NODES * CH];
__device__ __nv_bfloat16 g_aggHi[(size_t)N_NODES * CH];
__device__ __nv_bfloat16 g_aggLo[(size_t)N_NODES * CH];
__device__ __nv_bfloat16 g_hHiA[(size_t)N_NODES * CH];
__device__ __nv_bfloat16 g_hLoA[(size_t)N_NODES * CH];
__device__ __nv_bfloat16 g_hHiB[(size_t)N_NODES * CH];
__device__ __nv_bfloat16 g_hLoB[(size_t)N_NODES * CH];
// weights split hi/lo, ORIGINAL [k][n] layout: [layer][WlHi, WlLo, WrHi, WrLo]
__device__ __nv_bfloat16 g_wT[3][4][128 * 128];

// ---------------- helpers ----------------
__device__ __forceinline__ uint32_t smem_u32(const void* p) {
    uint32_t a;
    asm("{ .reg .u64 t; cvta.to.shared.u64 t, %1; cvt.u32.u64 %0, t; }"
        : "=r"(a) : "l"(p));
    return a;
}
__device__ __forceinline__ uint32_t bf16pack(float a, float b) {
    return (uint32_t)__bfloat16_as_ushort(__float2bfloat16_rn(a)) |
           ((uint32_t)__bfloat16_as_ushort(__float2bfloat16_rn(b)) << 16);
}

#define MMA_BF16(d, a, b0, b1) \
    asm volatile("mma.sync.aligned.m16n8k16.row.col.f32.bf16.bf16.f32 " \
        "{%0,%1,%2,%3}, {%4,%5,%6,%7}, {%8,%9}, {%0,%1,%2,%3};" \
        : "+f"((d)[0]), "+f"((d)[1]), "+f"((d)[2]), "+f"((d)[3]) \
        : "r"((a)[0]), "r"((a)[1]), "r"((a)[2]), "r"((a)[3]), "r"(b0), "r"(b1))

// A fragment: m16k16 from [m][k] tile (128B rows, SW128 swizzle)
__device__ __forceinline__ void ldmA(uint32_t a[4], uint32_t base, int mbase,
                                     int k0, int lane) {
    int t = lane >> 3, r = lane & 7;
    int m = mbase + (t & 1) * 8 + r;
    int kb = k0 + (t >> 1) * 8;
    uint32_t addr = base + (((uint32_t)(m * 128 + kb * 2)) ^ (uint32_t)((m & 7) << 4));
    asm volatile("ldmatrix.sync.aligned.m8n8.x4.shared.b16 {%0,%1,%2,%3}, [%4];"
                 : "=r"(a[0]), "=r"(a[1]), "=r"(a[2]), "=r"(a[3]) : "r"(addr));
}
// B fragments: two n8 tiles of k16 from [k][n] tile (256B rows, swizzled), trans
__device__ __forceinline__ void ldmB(uint32_t b[4], uint32_t base, int k0,
                                     int nb, int lane) {
    int t = lane >> 3, r = lane & 7;
    int k = k0 + (t & 1) * 8 + r;
    int n = nb + (t >> 1) * 8;
    uint32_t addr = base + (((uint32_t)(k * 256 + n * 2)) ^ (uint32_t)((k & 7) << 4));
    asm volatile("ldmatrix.sync.aligned.m8n8.x4.trans.shared.b16 {%0,%1,%2,%3}, [%4];"
                 : "=r"(b[0]), "=r"(b[1]), "=r"(b[2]), "=r"(b[3]) : "r"(addr));
}

// ---------------- small setup kernels ----------------
__global__ void zero_init_kernel() {
    int i = blockIdx.x * blockDim.x + threadIdx.x;
    if (i < N_NODES) g_deg[i] = 0;
}

__global__ void detect_kernel(const unsigned* __restrict__ w) {
    __shared__ int any32;
    if (threadIdx.x == 0) any32 = 0;
    __syncthreads();
    for (int i = threadIdx.x; i < 1024; i += blockDim.x) {
        if (w[2 * i + 1] != 0u) any32 = 1;  // benign race
    }
    __syncthreads();
    if (threadIdx.x == 0) g_is64 = any32 ? 0 : 1;
}

__device__ __forceinline__ int load_edge(const void* ei, int idx, int is64) {
    if (is64) return (int)((const long long*)ei)[idx];
    return ((const int*)ei)[idx];
}

__global__ void deg_kernel(const void* __restrict__ ei) {
    int e = blockIdx.x * blockDim.x + threadIdx.x;
    if (e >= N_EDGES) return;
    int d = load_edge(ei, N_EDGES + e, g_is64);
    atomicAdd(&g_deg[d], 1);
}

__global__ void bsum_kernel() {
    int i = blockIdx.x * SCAN_BLK + threadIdx.x;
    int v = (i < N_NODES) ? g_deg[i] : 0;
    int lane = threadIdx.x & 31, wid = threadIdx.x >> 5;
    __shared__ int ws[SCAN_BLK / 32];
#pragma unroll
    for (int off = 16; off > 0; off >>= 1)
        v += __shfl_down_sync(0xFFFFFFFFu, v, off);
    if (lane == 0) ws[wid] = v;
    __syncthreads();
    if (wid == 0) {
        v = (lane < SCAN_BLK / 32) ? ws[lane] : 0;
#pragma unroll
        for (int off = 16; off > 0; off >>= 1)
            v += __shfl_down_sync(0xFFFFFFFFu, v, off);
        if (lane == 0) g_bsum[blockIdx.x] = v;
    }
}

__global__ void bscan_kernel() {  // 1 block, 128 threads
    __shared__ int s[128];
    int t = threadIdx.x;
    int v = (t < NSCAN_BLOCKS) ? g_bsum[t] : 0;
    s[t] = v;
    __syncthreads();
    for (int off = 1; off < 128; off <<= 1) {
        int u = 0;
        if (t >= off) u = s[t - off];
        __syncthreads();
        if (t >= off) s[t] += u;
        __syncthreads();
    }
    if (t < NSCAN_BLOCKS) g_boff[t] = s[t] - v;
    if (t == NSCAN_BLOCKS - 1) g_rowptr[N_NODES] = s[t];
}

__global__ void scatter_scan_kernel() {
    int i = blockIdx.x * SCAN_BLK + threadIdx.x;
    int lane = threadIdx.x & 31, wid = threadIdx.x >> 5;
    int d = (i < N_NODES) ? g_deg[i] : 0;
    int incl = d;
#pragma unroll
    for (int off = 1; off < 32; off <<= 1) {
        int u = __shfl_up_sync(0xFFFFFFFFu, incl, off);
        if (lane >= off) incl += u;
    }
    __shared__ int wsum[SCAN_BLK / 32];
    __shared__ int wexcl[SCAN_BLK / 32];
    if (lane == 31) wsum[wid] = incl;
    __syncthreads();
    if (threadIdx.x == 0) {
        int run = 0;
#pragma unroll
        for (int w = 0; w < SCAN_BLK / 32; w++) { wexcl[w] = run; run += wsum[w]; }
    }
    __syncthreads();
    if (i < N_NODES) {
        int ex = incl - d + wexcl[wid] + g_boff[blockIdx.x];
        g_rowptr[i] = ex;
        g_cursor[i] = ex;
        g_invdeg[i] = (d > 0) ? (1.0f / (float)d) : 0.0f;
    }
}

__global__ void fill_kernel(const void* __restrict__ ei) {
    int e = blockIdx.x * blockDim.x + threadIdx.x;
    if (e >= N_EDGES) return;
    int is64 = g_is64;
    int s = load_edge(ei, e, is64);
    int d = load_edge(ei, N_EDGES + e, is64);
    int pos = atomicAdd(&g_cursor[d], 1);
    g_csr[pos] = s;
}

// ---------------- weight bf16 hi/lo split (layout unchanged: [k][n]) ----------------
__global__ void wconv_kernel(const float* __restrict__ Wl0, const float* __restrict__ Wr0,
                             const float* __restrict__ Wl1, const float* __restrict__ Wr1,
                             const float* __restrict__ Wl2, const float* __restrict__ Wr2) {
    const float* W[3][2] = {{Wl0, Wr0}, {Wl1, Wr1}, {Wl2, Wr2}};
    int id = blockIdx.x * blockDim.x + threadIdx.x;
    if (id >= 3 * 2 * 128 * 128) return;
    int l = id / 32768;
    int rem = id % 32768;
    int mat = rem / 16384;
    int e = rem % 16384;
    float w = W[l][mat][e];
    __nv_bfloat16 hi = __float2bfloat16_rn(w);
    __nv_bfloat16 lo = __float2bfloat16_rn(w - __bfloat162float(hi));
    g_wT[l][mat * 2 + 0][e] = hi;
    g_wT[l][mat * 2 + 1][e] = lo;
}

// ---------------- x -> bf16 hi/lo ----------------
__global__ void xconv_kernel(const float* __restrict__ x) {
    int i = blockIdx.x * blockDim.x + threadIdx.x;  // pair index
    if (i >= N_NODES * CH / 2) return;
    float2 v = ((const float2*)x)[i];
    __nv_bfloat16 h0 = __float2bfloat16_rn(v.x);
    __nv_bfloat16 h1 = __float2bfloat16_rn(v.y);
    ((uint32_t*)g_xHi)[i] = (uint32_t)__bfloat16_as_ushort(h0) |
                            ((uint32_t)__bfloat16_as_ushort(h1) << 16);
    ((uint32_t*)g_xLo)[i] = bf16pack(v.x - __bfloat162float(h0),
                                     v.y - __bfloat162float(h1));
}

// ---------------- aggregation: one warp per node -> bf16 hi/lo ----------------
__global__ void agg_kernel(const float* __restrict__ H) {
    int gt = blockIdx.x * blockDim.x + threadIdx.x;
    int node = gt >> 5;
    int lane = gt & 31;
    if (node >= N_NODES) return;
    int beg = g_rowptr[node];
    int end = g_rowptr[node + 1];
    float4 acc0 = make_float4(0.f, 0.f, 0.f, 0.f);
    float4 acc1 = acc0, acc2 = acc0, acc3 = acc0;
    int i = beg;
    for (; i + 4 <= end; i += 4) {
        int s0 = __ldg(&g_csr[i + 0]);
        int s1 = __ldg(&g_csr[i + 1]);
        int s2 = __ldg(&g_csr[i + 2]);
        int s3 = __ldg(&g_csr[i + 3]);
        float4 v0 = *(const float4*)(H + (size_t)s0 * CH + lane * 4);
        float4 v1 = *(const float4*)(H + (size_t)s1 * CH + lane * 4);
        float4 v2 = *(const float4*)(H + (size_t)s2 * CH + lane * 4);
        float4 v3 = *(const float4*)(H + (size_t)s3 * CH + lane * 4);
        acc0.x += v0.x; acc0.y += v0.y; acc0.z += v0.z; acc0.w += v0.w;
        acc1.x += v1.x; acc1.y += v1.y; acc1.z += v1.z; acc1.w += v1.w;
        acc2.x += v2.x; acc2.y += v2.y; acc2.z += v2.z; acc2.w += v2.w;
        acc3.x += v3.x; acc3.y += v3.y; acc3.z += v3.z; acc3.w += v3.w;
    }
    for (; i < end; i++) {
        int s0 = __ldg(&g_csr[i]);
        float4 v0 = *(const float4*)(H + (size_t)s0 * CH + lane * 4);
        acc0.x += v0.x; acc0.y += v0.y; acc0.z += v0.z; acc0.w += v0.w;
    }
    acc0.x += acc1.x + acc2.x + acc3.x;
    acc0.y += acc1.y + acc2.y + acc3.y;
    acc0.z += acc1.z + acc2.z + acc3.z;
    acc0.w += acc1.w + acc2.w + acc3.w;
    float s = g_invdeg[node];
    acc0.x *= s; acc0.y *= s; acc0.z *= s; acc0.w *= s;
    __nv_bfloat16 h0 = __float2bfloat16_rn(acc0.x);
    __nv_bfloat16 h1 = __float2bfloat16_rn(acc0.y);
    __nv_bfloat16 h2 = __float2bfloat16_rn(acc0.z);
    __nv_bfloat16 h3 = __float2bfloat16_rn(acc0.w);
    uint2 hi, lo;
    hi.x = (uint32_t)__bfloat16_as_ushort(h0) | ((uint32_t)__bfloat16_as_ushort(h1) << 16);
    hi.y = (uint32_t)__bfloat16_as_ushort(h2) | ((uint32_t)__bfloat16_as_ushort(h3) << 16);
    lo.x = bf16pack(acc0.x - __bfloat162float(h0), acc0.y - __bfloat162float(h1));
    lo.y = bf16pack(acc0.z - __bfloat162float(h2), acc0.w - __bfloat162float(h3));
    size_t off = (size_t)node * CH + lane * 4;
    *(uint2*)(g_aggHi + off) = hi;
    *(uint2*)(g_aggLo + off) = lo;
}

// ---------------- tensor-core fused dual GEMM via mma.sync ----------------
// Out = relu(Agg@Wl + bl + H@Wr); split precision: ah*wh + ah*wl + al*wh.
// CTA: 128x128 tile; 8 warps (4M x 2N), warp tile m32 x n64; K chunk 64.
#define SM_A 0                 // 4 arrays x [128][64] bf16 = 64 KB
#define SM_W 65536             // 4 mats   x [64][128] bf16 = 64 KB
#define TC_SMEM 131072

__global__ void __launch_bounds__(256, 1)
tc_gemm_kernel(const __nv_bfloat16* __restrict__ aggHi, const __nv_bfloat16* __restrict__ aggLo,
               const __nv_bfloat16* __restrict__ hHi, const __nv_bfloat16* __restrict__ hLo,
               const __nv_bfloat16* __restrict__ WT,  // [4][128*128] k-major
               const float* __restrict__ bl, float* __restrict__ Hout,
               __nv_bfloat16* __restrict__ hHiOut, __nv_bfloat16* __restrict__ hLoOut,
               int write_bf16) {
    extern __shared__ char smem[];
    uint32_t sb = smem_u32(smem);
    int tid = threadIdx.x;
    int lane = tid & 31;
    int warp = tid >> 5;
    int warpM = warp & 3;         // 0..3 -> m offset *32
    int warpN = warp >> 2;        // 0..1 -> n offset *64
    int row0 = blockIdx.x * 128;
    int mwbase = warpM * 32;
    int n0 = warpN * 64;

    const __nv_bfloat16* Asrc[4] = {aggHi, aggLo, hHi, hLo};

    float acc[2][8][4];
#pragma unroll
    for (int mi = 0; mi < 2; mi++)
#pragma unroll
        for (int j = 0; j < 8; j++)
#pragma unroll
            for (int q = 0; q < 4; q++) acc[mi][j][q] = 0.f;

    for (int kc = 0; kc < 128; kc += 64) {
        __syncthreads();
        // stage A: 4 arrays x 128 rows x 8 units(16B)
        for (int idx = tid; idx < 4096; idx += 256) {
            int arr = idx >> 10;
            int rem = idx & 1023;
            int r = rem >> 3;
            int u = rem & 7;
            int row = row0 + r;
            uint4 v = make_uint4(0u, 0u, 0u, 0u);
            if (row < N_NODES)
                v = *(const uint4*)(Asrc[arr] + (size_t)row * CH + kc + u * 8);
            uint32_t b = (uint32_t)(r * 128 + u * 16) ^ (uint32_t)((r & 7) << 4);
            *(uint4*)(smem + SM_A + arr * 16384 + b) = v;
        }
        // stage W: 4 mats x 64 k-rows x 16 units
        for (int idx = tid; idx < 4096; idx += 256) {
            int mat = idx >> 10;
            int rem = idx & 1023;
            int k = rem >> 4;
            int u = rem & 15;
            uint4 v = *(const uint4*)(WT + mat * 16384 + (kc + k) * 128 + u * 8);
            uint32_t b = (uint32_t)(k * 256 + u * 16) ^ (uint32_t)((k & 7) << 4);
            *(uint4*)(smem + SM_W + mat * 16384 + b) = v;
        }
        __syncthreads();

#pragma unroll
        for (int k16 = 0; k16 < 4; k16++) {
            int k0 = k16 * 16;
            // ---- left group: agg x Wl ----
            {
                uint32_t ah[2][4], al[2][4], bh[4][4], blo[4][4];
                ldmA(ah[0], sb + SM_A + 0 * 16384, mwbase, k0, lane);
                ldmA(ah[1], sb + SM_A + 0 * 16384, mwbase + 16, k0, lane);
                ldmA(al[0], sb + SM_A + 1 * 16384, mwbase, k0, lane);
                ldmA(al[1], sb + SM_A + 1 * 16384, mwbase + 16, k0, lane);
#pragma unroll
                for (int j = 0; j < 4; j++) {
                    ldmB(bh[j], sb + SM_W + 0 * 16384, k0, n0 + j * 16, lane);
                    ldmB(blo[j], sb + SM_W + 1 * 16384, k0, n0 + j * 16, lane);
                }
#pragma unroll
                for (int mi = 0; mi < 2; mi++)
#pragma unroll
                    for (int j = 0; j < 4; j++) {
                        MMA_BF16(acc[mi][2 * j],     ah[mi], bh[j][0], bh[j][1]);
                        MMA_BF16(acc[mi][2 * j + 1], ah[mi], bh[j][2], bh[j][3]);
                        MMA_BF16(acc[mi][2 * j],     ah[mi], blo[j][0], blo[j][1]);
                        MMA_BF16(acc[mi][2 * j + 1], ah[mi], blo[j][2], blo[j][3]);
                        MMA_BF16(acc[mi][2 * j],     al[mi], bh[j][0], bh[j][1]);
                        MMA_BF16(acc[mi][2 * j + 1], al[mi], bh[j][2], bh[j][3]);
                    }
            }
            // ---- right group: h x Wr ----
            {
                uint32_t ah[2][4], al[2][4], bh[4][4], blo[4][4];
                ldmA(ah[0], sb + SM_A + 2 * 16384, mwbase, k0, lane);
                ldmA(ah[1], sb + SM_A + 2 * 16384, mwbase + 16, k0, lane);
                ldmA(al[0], sb + SM_A + 3 * 16384, mwbase, k0, lane);
                ldmA(al[1], sb + SM_A + 3 * 16384, mwbase + 16, k0, lane);
#pragma unroll
                for (int j = 0; j < 4; j++) {
                    ldmB(bh[j], sb + SM_W + 2 * 16384, k0, n0 + j * 16, lane);
                    ldmB(blo[j], sb + SM_W + 3 * 16384, k0, n0 + j * 16, lane);
                }
#pragma unroll
                for (int mi = 0; mi < 2; mi++)
#pragma unroll
                    for (int j = 0; j < 4; j++) {
                        MMA_BF16(acc[mi][2 * j],     ah[mi], bh[j][0], bh[j][1]);
                        MMA_BF16(acc[mi][2 * j + 1], ah[mi], bh[j][2], bh[j][3]);
                        MMA_BF16(acc[mi][2 * j],     ah[mi], blo[j][0], blo[j][1]);
                        MMA_BF16(acc[mi][2 * j + 1], ah[mi], blo[j][2], blo[j][3]);
                        MMA_BF16(acc[mi][2 * j],     al[mi], bh[j][0], bh[j][1]);
                        MMA_BF16(acc[mi][2 * j + 1], al[mi], bh[j][2], bh[j][3]);
                    }
            }
        }
    }

    // ---- epilogue ----
    int g = lane >> 2, tg = lane & 3;
#pragma unroll
    for (int mi = 0; mi < 2; mi++) {
        int r1 = row0 + mwbase + mi * 16 + g;
#pragma unroll
        for (int j = 0; j < 8; j++) {
            int col = n0 + j * 8 + tg * 2;
            float2 bb = *(const float2*)(bl + col);
            float o0 = fmaxf(acc[mi][j][0] + bb.x, 0.f);
            float o1 = fmaxf(acc[mi][j][1] + bb.y, 0.f);
            float o2 = fmaxf(acc[mi][j][2] + bb.x, 0.f);
            float o3 = fmaxf(acc[mi][j][3] + bb.y, 0.f);
            if (r1 < N_NODES) {
                size_t off = (size_t)r1 * CH + col;
                *(float2*)(Hout + off) = make_float2(o0, o1);
                if (write_bf16) {
                    __nv_bfloat16 h0 = __float2bfloat16_rn(o0);
                    __nv_bfloat16 h1 = __float2bfloat16_rn(o1);
                    *(uint32_t*)(hHiOut + off) =
                        (uint32_t)__bfloat16_as_ushort(h0) |
                        ((uint32_t)__bfloat16_as_ushort(h1) << 16);
                    *(uint32_t*)(hLoOut + off) =
                        bf16pack(o0 - __bfloat162float(h0), o1 - __bfloat162float(h1));
                }
            }
            if (r1 + 8 < N_NODES) {
                size_t off = (size_t)(r1 + 8) * CH + col;
                *(float2*)(Hout + off) = make_float2(o2, o3);
                if (write_bf16) {
                    __nv_bfloat16 h2 = __float2bfloat16_rn(o2);
                    __nv_bfloat16 h3 = __float2bfloat16_rn(o3);
                    *(uint32_t*)(hHiOut + off) =
                        (uint32_t)__bfloat16_as_ushort(h2) |
                        ((uint32_t)__bfloat16_as_ushort(h3) << 16);
                    *(uint32_t*)(hLoOut + off) =
                        bf16pack(o2 - __bfloat162float(h2), o3 - __bfloat162float(h3));
                }
            }
        }
    }
}

// ---------------- head: logits = H @ Wh + bh, one warp per node ----------------
__global__ void head_kernel(const float* __restrict__ H, const float* __restrict__ Wh,
                            const float* __restrict__ bh, float* __restrict__ out) {
    __shared__ float sWh[CH];
    if (threadIdx.x < CH) sWh[threadIdx.x] = Wh[threadIdx.x];
    __syncthreads();
    int gt = blockIdx.x * blockDim.x + threadIdx.x;
    int node = gt >> 5;
    int lane = gt & 31;
    if (node >= N_NODES) return;
    float4 h = *(const float4*)(H + (size_t)node * CH + lane * 4);
    float4 w = *(const float4*)(sWh + lane * 4);
    float s = h.x * w.x + h.y * w.y + h.z * w.z + h.w * w.w;
#pragma unroll
    for (int off = 16; off > 0; off >>= 1)
        s += __shfl_down_sync(0xFFFFFFFFu, s, off);
    if (lane == 0) out[node] = s + bh[0];
}

// ---------------- launch ----------------
extern "C" void kernel_launch(void* const* d_in, const int* in_sizes, int n_in,
                              void* d_out, int out_size) {
    const float* x  = (const float*)d_in[0];
    const void*  ei = d_in[1];
    const float* Wl[3] = {(const float*)d_in[2], (const float*)d_in[5], (const float*)d_in[8]};
    const float* Wr[3] = {(const float*)d_in[3], (const float*)d_in[6], (const float*)d_in[9]};
    const float* bl[3] = {(const float*)d_in[4], (const float*)d_in[7], (const float*)d_in[10]};
    const float* Wh = (const float*)d_in[11];
    const float* bh = (const float*)d_in[12];
    float* out = (float*)d_out;

    cudaFuncSetAttribute(tc_gemm_kernel, cudaFuncAttributeMaxDynamicSharedMemorySize,
                         TC_SMEM);

    void *pA, *pB, *pW, *pXHi, *pXLo, *pAHi, *pALo, *pHiA, *pLoA, *pHiB, *pLoB;
    cudaGetSymbolAddress(&pA, g_bufA);
    cudaGetSymbolAddress(&pB, g_bufB);
    cudaGetSymbolAddress(&pW, g_wT);
    cudaGetSymbolAddress(&pXHi, g_xHi);
    cudaGetSymbolAddress(&pXLo, g_xLo);
    cudaGetSymbolAddress(&pAHi, g_aggHi);
    cudaGetSymbolAddress(&pALo, g_aggLo);
    cudaGetSymbolAddress(&pHiA, g_hHiA);
    cudaGetSymbolAddress(&pLoA, g_hLoA);
    cudaGetSymbolAddress(&pHiB, g_hHiB);
    cudaGetSymbolAddress(&pLoB, g_hLoB);
    float* bufA = (float*)pA;
    float* bufB = (float*)pB;
    const __nv_bfloat16* wT = (const __nv_bfloat16*)pW;

    // CSR build + weight/x conversion
    zero_init_kernel<<<(N_NODES + 255) / 256, 256>>>();
    detect_kernel<<<1, 256>>>((const unsigned*)ei);
    deg_kernel<<<(N_EDGES + 255) / 256, 256>>>(ei);
    bsum_kernel<<<NSCAN_BLOCKS, SCAN_BLK>>>();
    bscan_kernel<<<1, 128>>>();
    scatter_scan_kernel<<<NSCAN_BLOCKS, SCAN_BLK>>>();
    fill_kernel<<<(N_EDGES + 255) / 256, 256>>>(ei);
    wconv_kernel<<<(3 * 2 * 128 * 128 + 255) / 256, 256>>>(
        Wl[0], Wr[0], Wl[1], Wr[1], Wl[2], Wr[2]);
    xconv_kernel<<<(N_NODES * CH / 2 + 255) / 256, 256>>>(x);

    const int warp_grid = (N_NODES * 32 + 255) / 256;
    const int gemm_grid = (N_NODES + 127) / 128;  // 391

    const float* Hf_in[3] = {x, bufA, bufB};
    float* Hf_out[3] = {bufA, bufB, bufA};
    const __nv_bfloat16* hHi_in[3] = {(__nv_bfloat16*)pXHi, (__nv_bfloat16*)pHiA,
                                      (__nv_bfloat16*)pHiB};
    const __nv_bfloat16* hLo_in[3] = {(__nv_bfloat16*)pXLo, (__nv_bfloat16*)pLoA,
                                      (__nv_bfloat16*)pLoB};
    __nv_bfloat16* hHi_out[3] = {(__nv_bfloat16*)pHiA, (__nv_bfloat16*)pHiB,
                                 (__nv_bfloat16*)pHiA};
    __nv_bfloat16* hLo_out[3] = {(__nv_bfloat16*)pLoA, (__nv_bfloat16*)pLoB,
                                 (__nv_bfloat16*)pLoA};

    for (int l = 0; l < 3; l++) {
        agg_kernel<<<warp_grid, 256>>>(Hf_in[l]);
        tc_gemm_kernel<<<gemm_grid, 256, TC_SMEM>>>(
            (__nv_bfloat16*)pAHi, (__nv_bfloat16*)pALo, hHi_in[l], hLo_in[l],
            wT + (size_t)l * 4 * 16384, bl[l], Hf_out[l],
            hHi_out[l], hLo_out[l], (l < 2) ? 1 : 0);
    }
    head_kernel<<<warp_grid, 256>>>(Hf_out[2], Wh, bh, out);
}

// round 6
// speedup vs baseline: 1.8381x; 1.2800x over previous
#include <cuda_runtime.h>
#include <cuda_fp16.h>
#include <cstdint>

#define N_NODES 50000
#define N_EDGES 800000
#define CH 128

#define SCAN_BLK 512
#define NSCAN_BLOCKS ((N_NODES + SCAN_BLK - 1) / SCAN_BLK)  // 98

// ---------------- device scratch (no allocations allowed) ----------------
__device__ int   g_is64;
__device__ int   g_deg[N_NODES];
__device__ int   g_rowptr[N_NODES + 1];
__device__ int   g_cursor[N_NODES];
__device__ int   g_csr[N_EDGES];
__device__ int   g_bsum[NSCAN_BLOCKS];
__device__ int   g_boff[NSCAN_BLOCKS];
__device__ float g_invdeg[N_NODES];
__device__ float g_bufA[(size_t)N_NODES * CH];   // fp32 H ping
__device__ float g_bufB[(size_t)N_NODES * CH];   // fp32 H pong
__device__ __half g_xH [(size_t)N_NODES * CH];   // fp16 activations
__device__ __half g_aggH[(size_t)N_NODES * CH];
__device__ __half g_hHA[(size_t)N_NODES * CH];
__device__ __half g_hHB[(size_t)N_NODES * CH];
// weights split fp16 hi/lo, ORIGINAL [k][n] layout: [layer][WlH, WlL, WrH, WrL]
__device__ __half g_wS[3][4][128 * 128];

// ---------------- helpers ----------------
__device__ __forceinline__ uint32_t smem_u32(const void* p) {
    uint32_t a;
    asm("{ .reg .u64 t; cvta.to.shared.u64 t, %1; cvt.u32.u64 %0, t; }"
        : "=r"(a) : "l"(p));
    return a;
}
__device__ __forceinline__ uint32_t h2pack(float a, float b) {
    return (uint32_t)__half_as_ushort(__float2half_rn(a)) |
           ((uint32_t)__half_as_ushort(__float2half_rn(b)) << 16);
}

#define MMA_F16(d, a, b0, b1) \
    asm volatile("mma.sync.aligned.m16n8k16.row.col.f32.f16.f16.f32 " \
        "{%0,%1,%2,%3}, {%4,%5,%6,%7}, {%8,%9}, {%0,%1,%2,%3};" \
        : "+f"((d)[0]), "+f"((d)[1]), "+f"((d)[2]), "+f"((d)[3]) \
        : "r"((a)[0]), "r"((a)[1]), "r"((a)[2]), "r"((a)[3]), "r"(b0), "r"(b1))

// A fragment: m16k16 from [m][k] tile (128B rows, SW128 swizzle)
__device__ __forceinline__ void ldmA(uint32_t a[4], uint32_t base, int mbase,
                                     int k0, int lane) {
    int t = lane >> 3, r = lane & 7;
    int m = mbase + (t & 1) * 8 + r;
    int kb = k0 + (t >> 1) * 8;
    uint32_t addr = base + (((uint32_t)(m * 128 + kb * 2)) ^ (uint32_t)((m & 7) << 4));
    asm volatile("ldmatrix.sync.aligned.m8n8.x4.shared.b16 {%0,%1,%2,%3}, [%4];"
                 : "=r"(a[0]), "=r"(a[1]), "=r"(a[2]), "=r"(a[3]) : "r"(addr));
}
// B fragments: two n8 tiles of k16 from [k][n] tile (256B rows, swizzled), trans
__device__ __forceinline__ void ldmB(uint32_t b[4], uint32_t base, int k0,
                                     int nb, int lane) {
    int t = lane >> 3, r = lane & 7;
    int k = k0 + (t & 1) * 8 + r;
    int n = nb + (t >> 1) * 8;
    uint32_t addr = base + (((uint32_t)(k * 256 + n * 2)) ^ (uint32_t)((k & 7) << 4));
    asm volatile("ldmatrix.sync.aligned.m8n8.x4.trans.shared.b16 {%0,%1,%2,%3}, [%4];"
                 : "=r"(b[0]), "=r"(b[1]), "=r"(b[2]), "=r"(b[3]) : "r"(addr));
}

// ---------------- small setup kernels ----------------
__global__ void zero_init_kernel() {
    int i = blockIdx.x * blockDim.x + threadIdx.x;
    if (i < N_NODES) g_deg[i] = 0;
}

__global__ void detect_kernel(const unsigned* __restrict__ w) {
    __shared__ int any32;
    if (threadIdx.x == 0) any32 = 0;
    __syncthreads();
    for (int i = threadIdx.x; i < 1024; i += blockDim.x) {
        if (w[2 * i + 1] != 0u) any32 = 1;  // benign race
    }
    __syncthreads();
    if (threadIdx.x == 0) g_is64 = any32 ? 0 : 1;
}

__device__ __forceinline__ int load_edge(const void* ei, int idx, int is64) {
    if (is64) return (int)((const long long*)ei)[idx];
    return ((const int*)ei)[idx];
}

__global__ void deg_kernel(const void* __restrict__ ei) {
    int e = blockIdx.x * blockDim.x + threadIdx.x;
    if (e >= N_EDGES) return;
    int d = load_edge(ei, N_EDGES + e, g_is64);
    atomicAdd(&g_deg[d], 1);
}

__global__ void bsum_kernel() {
    int i = blockIdx.x * SCAN_BLK + threadIdx.x;
    int v = (i < N_NODES) ? g_deg[i] : 0;
    int lane = threadIdx.x & 31, wid = threadIdx.x >> 5;
    __shared__ int ws[SCAN_BLK / 32];
#pragma unroll
    for (int off = 16; off > 0; off >>= 1)
        v += __shfl_down_sync(0xFFFFFFFFu, v, off);
    if (lane == 0) ws[wid] = v;
    __syncthreads();
    if (wid == 0) {
        v = (lane < SCAN_BLK / 32) ? ws[lane] : 0;
#pragma unroll
        for (int off = 16; off > 0; off >>= 1)
            v += __shfl_down_sync(0xFFFFFFFFu, v, off);
        if (lane == 0) g_bsum[blockIdx.x] = v;
    }
}

__global__ void bscan_kernel() {  // 1 block, 128 threads
    __shared__ int s[128];
    int t = threadIdx.x;
    int v = (t < NSCAN_BLOCKS) ? g_bsum[t] : 0;
    s[t] = v;
    __syncthreads();
    for (int off = 1; off < 128; off <<= 1) {
        int u = 0;
        if (t >= off) u = s[t - off];
        __syncthreads();
        if (t >= off) s[t] += u;
        __syncthreads();
    }
    if (t < NSCAN_BLOCKS) g_boff[t] = s[t] - v;
    if (t == NSCAN_BLOCKS - 1) g_rowptr[N_NODES] = s[t];
}

__global__ void scatter_scan_kernel() {
    int i = blockIdx.x * SCAN_BLK + threadIdx.x;
    int lane = threadIdx.x & 31, wid = threadIdx.x >> 5;
    int d = (i < N_NODES) ? g_deg[i] : 0;
    int incl = d;
#pragma unroll
    for (int off = 1; off < 32; off <<= 1) {
        int u = __shfl_up_sync(0xFFFFFFFFu, incl, off);
        if (lane >= off) incl += u;
    }
    __shared__ int wsum[SCAN_BLK / 32];
    __shared__ int wexcl[SCAN_BLK / 32];
    if (lane == 31) wsum[wid] = incl;
    __syncthreads();
    if (threadIdx.x == 0) {
        int run = 0;
#pragma unroll
        for (int w = 0; w < SCAN_BLK / 32; w++) { wexcl[w] = run; run += wsum[w]; }
    }
    __syncthreads();
    if (i < N_NODES) {
        int ex = incl - d + wexcl[wid] + g_boff[blockIdx.x];
        g_rowptr[i] = ex;
        g_cursor[i] = ex;
        g_invdeg[i] = (d > 0) ? (1.0f / (float)d) : 0.0f;
    }
}

__global__ void fill_kernel(const void* __restrict__ ei) {
    int e = blockIdx.x * blockDim.x + threadIdx.x;
    if (e >= N_EDGES) return;
    int is64 = g_is64;
    int s = load_edge(ei, e, is64);
    int d = load_edge(ei, N_EDGES + e, is64);
    int pos = atomicAdd(&g_cursor[d], 1);
    g_csr[pos] = s;
}

// ---------------- weight fp16 hi/lo split (layout unchanged: [k][n]) ----------------
__global__ void wconv_kernel(const float* __restrict__ Wl0, const float* __restrict__ Wr0,
                             const float* __restrict__ Wl1, const float* __restrict__ Wr1,
                             const float* __restrict__ Wl2, const float* __restrict__ Wr2) {
    const float* W[3][2] = {{Wl0, Wr0}, {Wl1, Wr1}, {Wl2, Wr2}};
    int id = blockIdx.x * blockDim.x + threadIdx.x;
    if (id >= 3 * 2 * 128 * 128) return;
    int l = id / 32768;
    int rem = id % 32768;
    int mat = rem / 16384;
    int e = rem % 16384;
    float w = W[l][mat][e];
    __half hi = __float2half_rn(w);
    __half lo = __float2half_rn(w - __half2float(hi));
    g_wS[l][mat * 2 + 0][e] = hi;
    g_wS[l][mat * 2 + 1][e] = lo;
}

// ---------------- x -> fp16 ----------------
__global__ void xconv_kernel(const float* __restrict__ x) {
    int i = blockIdx.x * blockDim.x + threadIdx.x;  // pair index
    if (i >= N_NODES * CH / 2) return;
    float2 v = ((const float2*)x)[i];
    ((uint32_t*)g_xH)[i] = h2pack(v.x, v.y);
}

// ---------------- aggregation: one warp per node (fp32 gather) -> fp16 ----------------
__global__ void agg_kernel(const float* __restrict__ H) {
    int gt = blockIdx.x * blockDim.x + threadIdx.x;
    int node = gt >> 5;
    int lane = gt & 31;
    if (node >= N_NODES) return;
    int beg = g_rowptr[node];
    int end = g_rowptr[node + 1];
    float4 acc0 = make_float4(0.f, 0.f, 0.f, 0.f);
    float4 acc1 = acc0, acc2 = acc0, acc3 = acc0;
    int i = beg;
    for (; i + 4 <= end; i += 4) {
        int s0 = __ldg(&g_csr[i + 0]);
        int s1 = __ldg(&g_csr[i + 1]);
        int s2 = __ldg(&g_csr[i + 2]);
        int s3 = __ldg(&g_csr[i + 3]);
        float4 v0 = *(const float4*)(H + (size_t)s0 * CH + lane * 4);
        float4 v1 = *(const float4*)(H + (size_t)s1 * CH + lane * 4);
        float4 v2 = *(const float4*)(H + (size_t)s2 * CH + lane * 4);
        float4 v3 = *(const float4*)(H + (size_t)s3 * CH + lane * 4);
        acc0.x += v0.x; acc0.y += v0.y; acc0.z += v0.z; acc0.w += v0.w;
        acc1.x += v1.x; acc1.y += v1.y; acc1.z += v1.z; acc1.w += v1.w;
        acc2.x += v2.x; acc2.y += v2.y; acc2.z += v2.z; acc2.w += v2.w;
        acc3.x += v3.x; acc3.y += v3.y; acc3.z += v3.z; acc3.w += v3.w;
    }
    for (; i < end; i++) {
        int s0 = __ldg(&g_csr[i]);
        float4 v0 = *(const float4*)(H + (size_t)s0 * CH + lane * 4);
        acc0.x += v0.x; acc0.y += v0.y; acc0.z += v0.z; acc0.w += v0.w;
    }
    acc0.x += acc1.x + acc2.x + acc3.x;
    acc0.y += acc1.y + acc2.y + acc3.y;
    acc0.z += acc1.z + acc2.z + acc3.z;
    acc0.w += acc1.w + acc2.w + acc3.w;
    float s = g_invdeg[node];
    uint2 p;
    p.x = h2pack(acc0.x * s, acc0.y * s);
    p.y = h2pack(acc0.z * s, acc0.w * s);
    *(uint2*)(g_aggH + (size_t)node * CH + lane * 4) = p;
}

// ---------------- tensor-core fused dual GEMM via mma.sync (fp16) ----------------
// Out = relu(Agg@Wl + bl + H@Wr); weights split exact: x*(wh+wl), 2 products.
// CTA: 128x128 tile; 8 warps (4M x 2N), warp tile m32 x n64; K chunk 64.
#define SM_A 0                 // 2 arrays x [128][64] fp16 = 32 KB
#define SM_W 32768             // 4 mats   x [64][128] fp16 = 64 KB
#define TC_SMEM 98304

__global__ void __launch_bounds__(256, 2)
tc_gemm_kernel(const __half* __restrict__ aggH, const __half* __restrict__ hH,
               const __half* __restrict__ WS,  // [4][128*128] k-major: WlH,WlL,WrH,WrL
               const float* __restrict__ bl, float* __restrict__ Hout,
               __half* __restrict__ hHOut, int write_fp16) {
    extern __shared__ char smem[];
    uint32_t sb = smem_u32(smem);
    int tid = threadIdx.x;
    int lane = tid & 31;
    int warp = tid >> 5;
    int warpM = warp & 3;         // 0..3 -> m offset *32
    int warpN = warp >> 2;        // 0..1 -> n offset *64
    int row0 = blockIdx.x * 128;
    int mwbase = warpM * 32;
    int n0 = warpN * 64;

    const __half* Asrc[2] = {aggH, hH};

    float acc[2][8][4];
#pragma unroll
    for (int mi = 0; mi < 2; mi++)
#pragma unroll
        for (int j = 0; j < 8; j++)
#pragma unroll
            for (int q = 0; q < 4; q++) acc[mi][j][q] = 0.f;

    for (int kc = 0; kc < 128; kc += 64) {
        __syncthreads();
        // stage A: 2 arrays x 128 rows x 8 units(16B)
        for (int idx = tid; idx < 2048; idx += 256) {
            int arr = idx >> 10;
            int rem = idx & 1023;
            int r = rem >> 3;
            int u = rem & 7;
            int row = row0 + r;
            uint4 v = make_uint4(0u, 0u, 0u, 0u);
            if (row < N_NODES)
                v = *(const uint4*)(Asrc[arr] + (size_t)row * CH + kc + u * 8);
            uint32_t b = (uint32_t)(r * 128 + u * 16) ^ (uint32_t)((r & 7) << 4);
            *(uint4*)(smem + SM_A + arr * 16384 + b) = v;
        }
        // stage W: 4 mats x 64 k-rows x 16 units
        for (int idx = tid; idx < 4096; idx += 256) {
            int mat = idx >> 10;
            int rem = idx & 1023;
            int k = rem >> 4;
            int u = rem & 15;
            uint4 v = *(const uint4*)(WS + mat * 16384 + (kc + k) * 128 + u * 8);
            uint32_t b = (uint32_t)(k * 256 + u * 16) ^ (uint32_t)((k & 7) << 4);
            *(uint4*)(smem + SM_W + mat * 16384 + b) = v;
        }
        __syncthreads();

#pragma unroll
        for (int k16 = 0; k16 < 4; k16++) {
            int k0 = k16 * 16;
#pragma unroll
            for (int grp = 0; grp < 2; grp++) {   // 0: agg x Wl, 1: h x Wr
                uint32_t a[2][4];
                ldmA(a[0], sb + SM_A + grp * 16384, mwbase, k0, lane);
                ldmA(a[1], sb + SM_A + grp * 16384, mwbase + 16, k0, lane);
#pragma unroll
                for (int j = 0; j < 4; j++) {
                    uint32_t bh[4], blo[4];
                    ldmB(bh,  sb + SM_W + (grp * 2 + 0) * 16384, k0, n0 + j * 16, lane);
                    ldmB(blo, sb + SM_W + (grp * 2 + 1) * 16384, k0, n0 + j * 16, lane);
#pragma unroll
                    for (int mi = 0; mi < 2; mi++) {
                        MMA_F16(acc[mi][2 * j],     a[mi], bh[0],  bh[1]);
                        MMA_F16(acc[mi][2 * j + 1], a[mi], bh[2],  bh[3]);
                        MMA_F16(acc[mi][2 * j],     a[mi], blo[0], blo[1]);
                        MMA_F16(acc[mi][2 * j + 1], a[mi], blo[2], blo[3]);
                    }
                }
            }
        }
    }

    // ---- epilogue ----
    int g = lane >> 2, tg = lane & 3;
#pragma unroll
    for (int mi = 0; mi < 2; mi++) {
        int r1 = row0 + mwbase + mi * 16 + g;
#pragma unroll
        for (int j = 0; j < 8; j++) {
            int col = n0 + j * 8 + tg * 2;
            float2 bb = *(const float2*)(bl + col);
            float o0 = fmaxf(acc[mi][j][0] + bb.x, 0.f);
            float o1 = fmaxf(acc[mi][j][1] + bb.y, 0.f);
            float o2 = fmaxf(acc[mi][j][2] + bb.x, 0.f);
            float o3 = fmaxf(acc[mi][j][3] + bb.y, 0.f);
            if (r1 < N_NODES) {
                size_t off = (size_t)r1 * CH + col;
                *(float2*)(Hout + off) = make_float2(o0, o1);
                if (write_fp16) *(uint32_t*)(hHOut + off) = h2pack(o0, o1);
            }
            if (r1 + 8 < N_NODES) {
                size_t off = (size_t)(r1 + 8) * CH + col;
                *(float2*)(Hout + off) = make_float2(o2, o3);
                if (write_fp16) *(uint32_t*)(hHOut + off) = h2pack(o2, o3);
            }
        }
    }
}

// ---------------- head: logits = H @ Wh + bh, one warp per node ----------------
__global__ void head_kernel(const float* __restrict__ H, const float* __restrict__ Wh,
                            const float* __restrict__ bh, float* __restrict__ out) {
    __shared__ float sWh[CH];
    if (threadIdx.x < CH) sWh[threadIdx.x] = Wh[threadIdx.x];
    __syncthreads();
    int gt = blockIdx.x * blockDim.x + threadIdx.x;
    int node = gt >> 5;
    int lane = gt & 31;
    if (node >= N_NODES) return;
    float4 h = *(const float4*)(H + (size_t)node * CH + lane * 4);
    float4 w = *(const float4*)(sWh + lane * 4);
    float s = h.x * w.x + h.y * w.y + h.z * w.z + h.w * w.w;
#pragma unroll
    for (int off = 16; off > 0; off >>= 1)
        s += __shfl_down_sync(0xFFFFFFFFu, s, off);
    if (lane == 0) out[node] = s + bh[0];
}

// ---------------- launch ----------------
extern "C" void kernel_launch(void* const* d_in, const int* in_sizes, int n_in,
                              void* d_out, int out_size) {
    const float* x  = (const float*)d_in[0];
    const void*  ei = d_in[1];
    const float* Wl[3] = {(const float*)d_in[2], (const float*)d_in[5], (const float*)d_in[8]};
    const float* Wr[3] = {(const float*)d_in[3], (const float*)d_in[6], (const float*)d_in[9]};
    const float* bl[3] = {(const float*)d_in[4], (const float*)d_in[7], (const float*)d_in[10]};
    const float* Wh = (const float*)d_in[11];
    const float* bh = (const float*)d_in[12];
    float* out = (float*)d_out;

    cudaFuncSetAttribute(tc_gemm_kernel, cudaFuncAttributeMaxDynamicSharedMemorySize,
                         TC_SMEM);

    void *pA, *pB, *pW, *pXH, *pAH, *pHA, *pHB;
    cudaGetSymbolAddress(&pA, g_bufA);
    cudaGetSymbolAddress(&pB, g_bufB);
    cudaGetSymbolAddress(&pW, g_wS);
    cudaGetSymbolAddress(&pXH, g_xH);
    cudaGetSymbolAddress(&pAH, g_aggH);
    cudaGetSymbolAddress(&pHA, g_hHA);
    cudaGetSymbolAddress(&pHB, g_hHB);
    float* bufA = (float*)pA;
    float* bufB = (float*)pB;
    const __half* wS = (const __half*)pW;

    // CSR build + weight/x conversion
    zero_init_kernel<<<(N_NODES + 255) / 256, 256>>>();
    detect_kernel<<<1, 256>>>((const unsigned*)ei);
    deg_kernel<<<(N_EDGES + 255) / 256, 256>>>(ei);
    bsum_kernel<<<NSCAN_BLOCKS, SCAN_BLK>>>();
    bscan_kernel<<<1, 128>>>();
    scatter_scan_kernel<<<NSCAN_BLOCKS, SCAN_BLK>>>();
    fill_kernel<<<(N_EDGES + 255) / 256, 256>>>(ei);
    wconv_kernel<<<(3 * 2 * 128 * 128 + 255) / 256, 256>>>(
        Wl[0], Wr[0], Wl[1], Wr[1], Wl[2], Wr[2]);
    xconv_kernel<<<(N_NODES * CH / 2 + 255) / 256, 256>>>(x);

    const int warp_grid = (N_NODES * 32 + 255) / 256;
    const int gemm_grid = (N_NODES + 127) / 128;  // 391

    const float* Hf_in[3] = {x, bufA, bufB};
    float* Hf_out[3] = {bufA, bufB, bufA};
    const __half* hH_in[3] = {(__half*)pXH, (__half*)pHA, (__half*)pHB};
    __half* hH_out[3] = {(__half*)pHA, (__half*)pHB, (__half*)pHA};

    for (int l = 0; l < 3; l++) {
        agg_kernel<<<warp_grid, 256>>>(Hf_in[l]);
        tc_gemm_kernel<<<gemm_grid, 256, TC_SMEM>>>(
            (__half*)pAH, hH_in[l], wS + (size_t)l * 4 * 16384, bl[l],
            Hf_out[l], hH_out[l], (l < 2) ? 1 : 0);
    }
    head_kernel<<<warp_grid, 256>>>(Hf_out[2], Wh, bh, out);
}

// round 7
// speedup vs baseline: 1.8623x; 1.0132x over previous
#include <cuda_runtime.h>
#include <cuda_fp16.h>
#include <cstdint>

#define N_NODES 50000
#define N_EDGES 800000
#define CH 128

#define SCAN_BLK 512
#define NSCAN_BLOCKS ((N_NODES + SCAN_BLK - 1) / SCAN_BLK)  // 98

// ---------------- device scratch (no allocations allowed) ----------------
__device__ int   g_is64;
__device__ int   g_deg[N_NODES];
__device__ int   g_rowptr[N_NODES + 1];
__device__ int   g_cursor[N_NODES];
__device__ int   g_csr[N_EDGES];
__device__ int   g_bsum[NSCAN_BLOCKS];
__device__ int   g_boff[NSCAN_BLOCKS];
__device__ float g_invdeg[N_NODES];
__device__ __half g_xH [(size_t)N_NODES * CH];   // fp16 activations (layer input 0)
__device__ __half g_aggH[(size_t)N_NODES * CH];
__device__ __half g_hHA[(size_t)N_NODES * CH];   // fp16 H ping
__device__ __half g_hHB[(size_t)N_NODES * CH];   // fp16 H pong
// weights split fp16 hi/lo, ORIGINAL [k][n] layout: [layer][WlH, WlL, WrH, WrL]
__device__ __half g_wS[3][4][128 * 128];

// ---------------- helpers ----------------
__device__ __forceinline__ uint32_t smem_u32(const void* p) {
    uint32_t a;
    asm("{ .reg .u64 t; cvta.to.shared.u64 t, %1; cvt.u32.u64 %0, t; }"
        : "=r"(a) : "l"(p));
    return a;
}
__device__ __forceinline__ uint32_t h2pack(float a, float b) {
    return (uint32_t)__half_as_ushort(__float2half_rn(a)) |
           ((uint32_t)__half_as_ushort(__float2half_rn(b)) << 16);
}
__device__ __forceinline__ float2 h2unpack(uint32_t v) {
    __half2 h = *(__half2*)&v;
    return __half22float2(h);
}

#define MMA_F16(d, a, b0, b1) \
    asm volatile("mma.sync.aligned.m16n8k16.row.col.f32.f16.f16.f32 " \
        "{%0,%1,%2,%3}, {%4,%5,%6,%7}, {%8,%9}, {%0,%1,%2,%3};" \
        : "+f"((d)[0]), "+f"((d)[1]), "+f"((d)[2]), "+f"((d)[3]) \
        : "r"((a)[0]), "r"((a)[1]), "r"((a)[2]), "r"((a)[3]), "r"(b0), "r"(b1))

// A fragment: m16k16 from [m][k] tile (128B rows, SW128 swizzle)
__device__ __forceinline__ void ldmA(uint32_t a[4], uint32_t base, int mbase,
                                     int k0, int lane) {
    int t = lane >> 3, r = lane & 7;
    int m = mbase + (t & 1) * 8 + r;
    int kb = k0 + (t >> 1) * 8;
    uint32_t addr = base + (((uint32_t)(m * 128 + kb * 2)) ^ (uint32_t)((m & 7) << 4));
    asm volatile("ldmatrix.sync.aligned.m8n8.x4.shared.b16 {%0,%1,%2,%3}, [%4];"
                 : "=r"(a[0]), "=r"(a[1]), "=r"(a[2]), "=r"(a[3]) : "r"(addr));
}
// B fragments: two n8 tiles of k16 from [k][n] tile (256B rows, swizzled), trans
__device__ __forceinline__ void ldmB(uint32_t b[4], uint32_t base, int k0,
                                     int nb, int lane) {
    int t = lane >> 3, r = lane & 7;
    int k = k0 + (t & 1) * 8 + r;
    int n = nb + (t >> 1) * 8;
    uint32_t addr = base + (((uint32_t)(k * 256 + n * 2)) ^ (uint32_t)((k & 7) << 4));
    asm volatile("ldmatrix.sync.aligned.m8n8.x4.trans.shared.b16 {%0,%1,%2,%3}, [%4];"
                 : "=r"(b[0]), "=r"(b[1]), "=r"(b[2]), "=r"(b[3]) : "r"(addr));
}

// ---------------- small setup kernels ----------------
__global__ void zero_init_kernel() {
    int i = blockIdx.x * blockDim.x + threadIdx.x;
    if (i < N_NODES) g_deg[i] = 0;
}

__global__ void detect_kernel(const unsigned* __restrict__ w) {
    __shared__ int any32;
    if (threadIdx.x == 0) any32 = 0;
    __syncthreads();
    for (int i = threadIdx.x; i < 1024; i += blockDim.x) {
        if (w[2 * i + 1] != 0u) any32 = 1;  // benign race
    }
    __syncthreads();
    if (threadIdx.x == 0) g_is64 = any32 ? 0 : 1;
}

__device__ __forceinline__ int load_edge(const void* ei, int idx, int is64) {
    if (is64) return (int)((const long long*)ei)[idx];
    return ((const int*)ei)[idx];
}

__global__ void deg_kernel(const void* __restrict__ ei) {
    int e = blockIdx.x * blockDim.x + threadIdx.x;
    if (e >= N_EDGES) return;
    int d = load_edge(ei, N_EDGES + e, g_is64);
    atomicAdd(&g_deg[d], 1);
}

__global__ void bsum_kernel() {
    int i = blockIdx.x * SCAN_BLK + threadIdx.x;
    int v = (i < N_NODES) ? g_deg[i] : 0;
    int lane = threadIdx.x & 31, wid = threadIdx.x >> 5;
    __shared__ int ws[SCAN_BLK / 32];
#pragma unroll
    for (int off = 16; off > 0; off >>= 1)
        v += __shfl_down_sync(0xFFFFFFFFu, v, off);
    if (lane == 0) ws[wid] = v;
    __syncthreads();
    if (wid == 0) {
        v = (lane < SCAN_BLK / 32) ? ws[lane] : 0;
#pragma unroll
        for (int off = 16; off > 0; off >>= 1)
            v += __shfl_down_sync(0xFFFFFFFFu, v, off);
        if (lane == 0) g_bsum[blockIdx.x] = v;
    }
}

__global__ void bscan_kernel() {  // 1 block, 128 threads
    __shared__ int s[128];
    int t = threadIdx.x;
    int v = (t < NSCAN_BLOCKS) ? g_bsum[t] : 0;
    s[t] = v;
    __syncthreads();
    for (int off = 1; off < 128; off <<= 1) {
        int u = 0;
        if (t >= off) u = s[t - off];
        __syncthreads();
        if (t >= off) s[t] += u;
        __syncthreads();
    }
    if (t < NSCAN_BLOCKS) g_boff[t] = s[t] - v;
    if (t == NSCAN_BLOCKS - 1) g_rowptr[N_NODES] = s[t];
}

__global__ void scatter_scan_kernel() {
    int i = blockIdx.x * SCAN_BLK + threadIdx.x;
    int lane = threadIdx.x & 31, wid = threadIdx.x >> 5;
    int d = (i < N_NODES) ? g_deg[i] : 0;
    int incl = d;
#pragma unroll
    for (int off = 1; off < 32; off <<= 1) {
        int u = __shfl_up_sync(0xFFFFFFFFu, incl, off);
        if (lane >= off) incl += u;
    }
    __shared__ int wsum[SCAN_BLK / 32];
    __shared__ int wexcl[SCAN_BLK / 32];
    if (lane == 31) wsum[wid] = incl;
    __syncthreads();
    if (threadIdx.x == 0) {
        int run = 0;
#pragma unroll
        for (int w = 0; w < SCAN_BLK / 32; w++) { wexcl[w] = run; run += wsum[w]; }
    }
    __syncthreads();
    if (i < N_NODES) {
        int ex = incl - d + wexcl[wid] + g_boff[blockIdx.x];
        g_rowptr[i] = ex;
        g_cursor[i] = ex;
        g_invdeg[i] = (d > 0) ? (1.0f / (float)d) : 0.0f;
    }
}

__global__ void fill_kernel(const void* __restrict__ ei) {
    int e = blockIdx.x * blockDim.x + threadIdx.x;
    if (e >= N_EDGES) return;
    int is64 = g_is64;
    int s = load_edge(ei, e, is64);
    int d = load_edge(ei, N_EDGES + e, is64);
    int pos = atomicAdd(&g_cursor[d], 1);
    g_csr[pos] = s;
}

// ---------------- weight fp16 hi/lo split (layout unchanged: [k][n]) ----------------
__global__ void wconv_kernel(const float* __restrict__ Wl0, const float* __restrict__ Wr0,
                             const float* __restrict__ Wl1, const float* __restrict__ Wr1,
                             const float* __restrict__ Wl2, const float* __restrict__ Wr2) {
    const float* W[3][2] = {{Wl0, Wr0}, {Wl1, Wr1}, {Wl2, Wr2}};
    int id = blockIdx.x * blockDim.x + threadIdx.x;
    if (id >= 3 * 2 * 128 * 128) return;
    int l = id / 32768;
    int rem = id % 32768;
    int mat = rem / 16384;
    int e = rem % 16384;
    float w = W[l][mat][e];
    __half hi = __float2half_rn(w);
    __half lo = __float2half_rn(w - __half2float(hi));
    g_wS[l][mat * 2 + 0][e] = hi;
    g_wS[l][mat * 2 + 1][e] = lo;
}

// ---------------- x -> fp16 ----------------
__global__ void xconv_kernel(const float* __restrict__ x) {
    int i = blockIdx.x * blockDim.x + threadIdx.x;  // pair index
    if (i >= N_NODES * CH / 2) return;
    float2 v = ((const float2*)x)[i];
    ((uint32_t*)g_xH)[i] = h2pack(v.x, v.y);
}

// ---------------- aggregation: one warp per node, fp16 gather, fp32 accum ----------------
__global__ void agg_kernel(const __half* __restrict__ H) {
    int gt = blockIdx.x * blockDim.x + threadIdx.x;
    int node = gt >> 5;
    int lane = gt & 31;
    if (node >= N_NODES) return;
    int beg = g_rowptr[node];
    int end = g_rowptr[node + 1];
    float4 acc0 = make_float4(0.f, 0.f, 0.f, 0.f);
    float4 acc1 = acc0, acc2 = acc0, acc3 = acc0;
    int i = beg;
    for (; i + 4 <= end; i += 4) {
        int s0 = __ldg(&g_csr[i + 0]);
        int s1 = __ldg(&g_csr[i + 1]);
        int s2 = __ldg(&g_csr[i + 2]);
        int s3 = __ldg(&g_csr[i + 3]);
        uint2 r0 = *(const uint2*)(H + (size_t)s0 * CH + lane * 4);
        uint2 r1 = *(const uint2*)(H + (size_t)s1 * CH + lane * 4);
        uint2 r2 = *(const uint2*)(H + (size_t)s2 * CH + lane * 4);
        uint2 r3 = *(const uint2*)(H + (size_t)s3 * CH + lane * 4);
        float2 a0 = h2unpack(r0.x), b0 = h2unpack(r0.y);
        float2 a1 = h2unpack(r1.x), b1 = h2unpack(r1.y);
        float2 a2 = h2unpack(r2.x), b2 = h2unpack(r2.y);
        float2 a3 = h2unpack(r3.x), b3 = h2unpack(r3.y);
        acc0.x += a0.x; acc0.y += a0.y; acc0.z += b0.x; acc0.w += b0.y;
        acc1.x += a1.x; acc1.y += a1.y; acc1.z += b1.x; acc1.w += b1.y;
        acc2.x += a2.x; acc2.y += a2.y; acc2.z += b2.x; acc2.w += b2.y;
        acc3.x += a3.x; acc3.y += a3.y; acc3.z += b3.x; acc3.w += b3.y;
    }
    for (; i < end; i++) {
        int s0 = __ldg(&g_csr[i]);
        uint2 r0 = *(const uint2*)(H + (size_t)s0 * CH + lane * 4);
        float2 a0 = h2unpack(r0.x), b0 = h2unpack(r0.y);
        acc0.x += a0.x; acc0.y += a0.y; acc0.z += b0.x; acc0.w += b0.y;
    }
    acc0.x += acc1.x + acc2.x + acc3.x;
    acc0.y += acc1.y + acc2.y + acc3.y;
    acc0.z += acc1.z + acc2.z + acc3.z;
    acc0.w += acc1.w + acc2.w + acc3.w;
    float s = g_invdeg[node];
    uint2 p;
    p.x = h2pack(acc0.x * s, acc0.y * s);
    p.y = h2pack(acc0.z * s, acc0.w * s);
    *(uint2*)(g_aggH + (size_t)node * CH + lane * 4) = p;
}

// ---------------- tensor-core fused dual GEMM via mma.sync (fp16) ----------------
// Out = relu(Agg@Wl + bl + H@Wr); weights split exact: x*(wh+wl), 2 products.
// CTA: 128x128 tile; 8 warps (4M x 2N), warp tile m32 x n64; K chunk 64.
#define SM_A 0                 // 2 arrays x [128][64] fp16 = 32 KB
#define SM_W 32768             // 4 mats   x [64][128] fp16 = 64 KB
#define TC_SMEM 98304

__global__ void __launch_bounds__(256, 2)
tc_gemm_kernel(const __half* __restrict__ aggH, const __half* __restrict__ hH,
               const __half* __restrict__ WS,  // [4][128*128] k-major: WlH,WlL,WrH,WrL
               const float* __restrict__ bl, __half* __restrict__ hHOut) {
    extern __shared__ char smem[];
    uint32_t sb = smem_u32(smem);
    int tid = threadIdx.x;
    int lane = tid & 31;
    int warp = tid >> 5;
    int warpM = warp & 3;         // 0..3 -> m offset *32
    int warpN = warp >> 2;        // 0..1 -> n offset *64
    int row0 = blockIdx.x * 128;
    int mwbase = warpM * 32;
    int n0 = warpN * 64;

    const __half* Asrc[2] = {aggH, hH};

    float acc[2][8][4];
#pragma unroll
    for (int mi = 0; mi < 2; mi++)
#pragma unroll
        for (int j = 0; j < 8; j++)
#pragma unroll
            for (int q = 0; q < 4; q++) acc[mi][j][q] = 0.f;

    for (int kc = 0; kc < 128; kc += 64) {
        __syncthreads();
        // stage A: 2 arrays x 128 rows x 8 units(16B)
        for (int idx = tid; idx < 2048; idx += 256) {
            int arr = idx >> 10;
            int rem = idx & 1023;
            int r = rem >> 3;
            int u = rem & 7;
            int row = row0 + r;
            uint4 v = make_uint4(0u, 0u, 0u, 0u);
            if (row < N_NODES)
                v = *(const uint4*)(Asrc[arr] + (size_t)row * CH + kc + u * 8);
            uint32_t b = (uint32_t)(r * 128 + u * 16) ^ (uint32_t)((r & 7) << 4);
            *(uint4*)(smem + SM_A + arr * 16384 + b) = v;
        }
        // stage W: 4 mats x 64 k-rows x 16 units
        for (int idx = tid; idx < 4096; idx += 256) {
            int mat = idx >> 10;
            int rem = idx & 1023;
            int k = rem >> 4;
            int u = rem & 15;
            uint4 v = *(const uint4*)(WS + mat * 16384 + (kc + k) * 128 + u * 8);
            uint32_t b = (uint32_t)(k * 256 + u * 16) ^ (uint32_t)((k & 7) << 4);
            *(uint4*)(smem + SM_W + mat * 16384 + b) = v;
        }
        __syncthreads();

#pragma unroll
        for (int k16 = 0; k16 < 4; k16++) {
            int k0 = k16 * 16;
#pragma unroll
            for (int grp = 0; grp < 2; grp++) {   // 0: agg x Wl, 1: h x Wr
                uint32_t a[2][4];
                ldmA(a[0], sb + SM_A + grp * 16384, mwbase, k0, lane);
                ldmA(a[1], sb + SM_A + grp * 16384, mwbase + 16, k0, lane);
#pragma unroll
                for (int j = 0; j < 4; j++) {
                    uint32_t bh[4], blo[4];
                    ldmB(bh,  sb + SM_W + (grp * 2 + 0) * 16384, k0, n0 + j * 16, lane);
                    ldmB(blo, sb + SM_W + (grp * 2 + 1) * 16384, k0, n0 + j * 16, lane);
#pragma unroll
                    for (int mi = 0; mi < 2; mi++) {
                        MMA_F16(acc[mi][2 * j],     a[mi], bh[0],  bh[1]);
                        MMA_F16(acc[mi][2 * j + 1], a[mi], bh[2],  bh[3]);
                        MMA_F16(acc[mi][2 * j],     a[mi], blo[0], blo[1]);
                        MMA_F16(acc[mi][2 * j + 1], a[mi], blo[2], blo[3]);
                    }
                }
            }
        }
    }

    // ---- epilogue: bias + relu -> fp16 ----
    int g = lane >> 2, tg = lane & 3;
#pragma unroll
    for (int mi = 0; mi < 2; mi++) {
        int r1 = row0 + mwbase + mi * 16 + g;
#pragma unroll
        for (int j = 0; j < 8; j++) {
            int col = n0 + j * 8 + tg * 2;
            float2 bb = *(const float2*)(bl + col);
            float o0 = fmaxf(acc[mi][j][0] + bb.x, 0.f);
            float o1 = fmaxf(acc[mi][j][1] + bb.y, 0.f);
            float o2 = fmaxf(acc[mi][j][2] + bb.x, 0.f);
            float o3 = fmaxf(acc[mi][j][3] + bb.y, 0.f);
            if (r1 < N_NODES)
                *(uint32_t*)(hHOut + (size_t)r1 * CH + col) = h2pack(o0, o1);
            if (r1 + 8 < N_NODES)
                *(uint32_t*)(hHOut + (size_t)(r1 + 8) * CH + col) = h2pack(o2, o3);
        }
    }
}

// ---------------- head: logits = H @ Wh + bh, one warp per node (fp16 H) ----------------
__global__ void head_kernel(const __half* __restrict__ H, const float* __restrict__ Wh,
                            const float* __restrict__ bh, float* __restrict__ out) {
    __shared__ float sWh[CH];
    if (threadIdx.x < CH) sWh[threadIdx.x] = Wh[threadIdx.x];
    __syncthreads();
    int gt = blockIdx.x * blockDim.x + threadIdx.x;
    int node = gt >> 5;
    int lane = gt & 31;
    if (node >= N_NODES) return;
    uint2 r = *(const uint2*)(H + (size_t)node * CH + lane * 4);
    float2 a = h2unpack(r.x), b = h2unpack(r.y);
    float4 w = *(const float4*)(sWh + lane * 4);
    float s = a.x * w.x + a.y * w.y + b.x * w.z + b.y * w.w;
#pragma unroll
    for (int off = 16; off > 0; off >>= 1)
        s += __shfl_down_sync(0xFFFFFFFFu, s, off);
    if (lane == 0) out[node] = s + bh[0];
}

// ---------------- launch ----------------
extern "C" void kernel_launch(void* const* d_in, const int* in_sizes, int n_in,
                              void* d_out, int out_size) {
    const float* x  = (const float*)d_in[0];
    const void*  ei = d_in[1];
    const float* Wl[3] = {(const float*)d_in[2], (const float*)d_in[5], (const float*)d_in[8]};
    const float* Wr[3] = {(const float*)d_in[3], (const float*)d_in[6], (const float*)d_in[9]};
    const float* bl[3] = {(const float*)d_in[4], (const float*)d_in[7], (const float*)d_in[10]};
    const float* Wh = (const float*)d_in[11];
    const float* bh = (const float*)d_in[12];
    float* out = (float*)d_out;

    cudaFuncSetAttribute(tc_gemm_kernel, cudaFuncAttributeMaxDynamicSharedMemorySize,
                         TC_SMEM);

    void *pW, *pXH, *pAH, *pHA, *pHB;
    cudaGetSymbolAddress(&pW, g_wS);
    cudaGetSymbolAddress(&pXH, g_xH);
    cudaGetSymbolAddress(&pAH, g_aggH);
    cudaGetSymbolAddress(&pHA, g_hHA);
    cudaGetSymbolAddress(&pHB, g_hHB);
    const __half* wS = (const __half*)pW;

    // CSR build + weight/x conversion
    zero_init_kernel<<<(N_NODES + 255) / 256, 256>>>();
    detect_kernel<<<1, 256>>>((const unsigned*)ei);
    deg_kernel<<<(N_EDGES + 255) / 256, 256>>>(ei);
    bsum_kernel<<<NSCAN_BLOCKS, SCAN_BLK>>>();
    bscan_kernel<<<1, 128>>>();
    scatter_scan_kernel<<<NSCAN_BLOCKS, SCAN_BLK>>>();
    fill_kernel<<<(N_EDGES + 255) / 256, 256>>>(ei);
    wconv_kernel<<<(3 * 2 * 128 * 128 + 255) / 256, 256>>>(
        Wl[0], Wr[0], Wl[1], Wr[1], Wl[2], Wr[2]);
    xconv_kernel<<<(N_NODES * CH / 2 + 255) / 256, 256>>>(x);

    const int warp_grid = (N_NODES * 32 + 255) / 256;
    const int gemm_grid = (N_NODES + 127) / 128;  // 391

    const __half* hH_in[3] = {(__half*)pXH, (__half*)pHA, (__half*)pHB};
    __half* hH_out[3] = {(__half*)pHA, (__half*)pHB, (__half*)pHA};

    for (int l = 0; l < 3; l++) {
        agg_kernel<<<warp_grid, 256>>>(hH_in[l]);
        tc_gemm_kernel<<<gemm_grid, 256, TC_SMEM>>>(
            (__half*)pAH, hH_in[l], wS + (size_t)l * 4 * 16384, bl[l], hH_out[l]);
    }
    head_kernel<<<warp_grid, 256>>>(hH_out[2], Wh, bh, out);
}

// round 9
// speedup vs baseline: 1.9060x; 1.0234x over previous
#include <cuda_runtime.h>
#include <cuda_fp16.h>
#include <cstdint>

#define N_NODES 50000
#define N_EDGES 800000
#define CH 128

#define SCAN_BLK 512
#define NSCAN_BLOCKS ((N_NODES + SCAN_BLK - 1) / SCAN_BLK)  // 98

// ---------------- device scratch (no allocations allowed) ----------------
__device__ int   g_is64;
__device__ int   g_deg[N_NODES];
__device__ int   g_rowptr[N_NODES + 1];
__device__ int   g_cursor[N_NODES];
__device__ int   g_csr[N_EDGES];
__device__ int   g_bsum[NSCAN_BLOCKS];
__device__ int   g_boff[NSCAN_BLOCKS];
__device__ float g_invdeg[N_NODES];
__device__ __half g_xH [(size_t)N_NODES * CH];   // fp16 activations (layer input 0)
__device__ __half g_aggH[(size_t)N_NODES * CH];
__device__ __half g_hHA[(size_t)N_NODES * CH];   // fp16 H ping
__device__ __half g_hHB[(size_t)N_NODES * CH];   // fp16 H pong
// weights split fp16 hi/lo, ORIGINAL [k][n] layout: [layer][WlH, WlL, WrH, WrL]
__device__ __half g_wS[3][4][128 * 128];

// ---------------- helpers ----------------
__device__ __forceinline__ uint32_t smem_u32(const void* p) {
    uint32_t a;
    asm("{ .reg .u64 t; cvta.to.shared.u64 t, %1; cvt.u32.u64 %0, t; }"
        : "=r"(a) : "l"(p));
    return a;
}
__device__ __forceinline__ uint32_t h2pack(float a, float b) {
    return (uint32_t)__half_as_ushort(__float2half_rn(a)) |
           ((uint32_t)__half_as_ushort(__float2half_rn(b)) << 16);
}
__device__ __forceinline__ float2 h2unpack(uint32_t v) {
    __half2 h = *(__half2*)&v;
    return __half22float2(h);
}

#define MMA_F16(d, a, b0, b1) \
    asm volatile("mma.sync.aligned.m16n8k16.row.col.f32.f16.f16.f32 " \
        "{%0,%1,%2,%3}, {%4,%5,%6,%7}, {%8,%9}, {%0,%1,%2,%3};" \
        : "+f"((d)[0]), "+f"((d)[1]), "+f"((d)[2]), "+f"((d)[3]) \
        : "r"((a)[0]), "r"((a)[1]), "r"((a)[2]), "r"((a)[3]), "r"(b0), "r"(b1))

// A fragment: m16k16 from [m][k] tile (128B rows, SW128 swizzle)
__device__ __forceinline__ void ldmA(uint32_t a[4], uint32_t base, int mbase,
                                     int k0, int lane) {
    int t = lane >> 3, r = lane & 7;
    int m = mbase + (t & 1) * 8 + r;
    int kb = k0 + (t >> 1) * 8;
    uint32_t addr = base + (((uint32_t)(m * 128 + kb * 2)) ^ (uint32_t)((m & 7) << 4));
    asm volatile("ldmatrix.sync.aligned.m8n8.x4.shared.b16 {%0,%1,%2,%3}, [%4];"
                 : "=r"(a[0]), "=r"(a[1]), "=r"(a[2]), "=r"(a[3]) : "r"(addr));
}
// B fragments: two n8 tiles of k16 from [k][n] tile (256B rows, swizzled), trans
__device__ __forceinline__ void ldmB(uint32_t b[4], uint32_t base, int k0,
                                     int nb, int lane) {
    int t = lane >> 3, r = lane & 7;
    int k = k0 + (t & 1) * 8 + r;
    int n = nb + (t >> 1) * 8;
    uint32_t addr = base + (((uint32_t)(k * 256 + n * 2)) ^ (uint32_t)((k & 7) << 4));
    asm volatile("ldmatrix.sync.aligned.m8n8.x4.trans.shared.b16 {%0,%1,%2,%3}, [%4];"
                 : "=r"(b[0]), "=r"(b[1]), "=r"(b[2]), "=r"(b[3]) : "r"(addr));
}

// ---------------- fused zero + dtype-detect ----------------
__global__ void zero_detect_kernel(const unsigned* __restrict__ w) {
    int i = blockIdx.x * blockDim.x + threadIdx.x;
    if (i < N_NODES) g_deg[i] = 0;
    if (blockIdx.x == 0) {
        __shared__ int any32;
        if (threadIdx.x == 0) any32 = 0;
        __syncthreads();
        for (int j = threadIdx.x; j < 1024; j += blockDim.x) {
            if (w[2 * j + 1] != 0u) any32 = 1;  // benign race
        }
        __syncthreads();
        if (threadIdx.x == 0) g_is64 = any32 ? 0 : 1;
    }
}

__device__ __forceinline__ int load_edge(const void* ei, int idx, int is64) {
    if (is64) return (int)((const long long*)ei)[idx];
    return ((const int*)ei)[idx];
}

__global__ void deg_kernel(const void* __restrict__ ei) {
    int e = blockIdx.x * blockDim.x + threadIdx.x;
    if (e >= N_EDGES) return;
    int d = load_edge(ei, N_EDGES + e, g_is64);
    atomicAdd(&g_deg[d], 1);
}

__global__ void bsum_kernel() {
    int i = blockIdx.x * SCAN_BLK + threadIdx.x;
    int v = (i < N_NODES) ? g_deg[i] : 0;
    int lane = threadIdx.x & 31, wid = threadIdx.x >> 5;
    __shared__ int ws[SCAN_BLK / 32];
#pragma unroll
    for (int off = 16; off > 0; off >>= 1)
        v += __shfl_down_sync(0xFFFFFFFFu, v, off);
    if (lane == 0) ws[wid] = v;
    __syncthreads();
    if (wid == 0) {
        v = (lane < SCAN_BLK / 32) ? ws[lane] : 0;
#pragma unroll
        for (int off = 16; off > 0; off >>= 1)
            v += __shfl_down_sync(0xFFFFFFFFu, v, off);
        if (lane == 0) g_bsum[blockIdx.x] = v;
    }
}

__global__ void bscan_kernel() {  // 1 block, 128 threads
    __shared__ int s[128];
    int t = threadIdx.x;
    int v = (t < NSCAN_BLOCKS) ? g_bsum[t] : 0;
    s[t] = v;
    __syncthreads();
    for (int off = 1; off < 128; off <<= 1) {
        int u = 0;
        if (t >= off) u = s[t - off];
        __syncthreads();
        if (t >= off) s[t] += u;
        __syncthreads();
    }
    if (t < NSCAN_BLOCKS) g_boff[t] = s[t] - v;
    if (t == NSCAN_BLOCKS - 1) g_rowptr[N_NODES] = s[t];
}

__global__ void scatter_scan_kernel() {
    int i = blockIdx.x * SCAN_BLK + threadIdx.x;
    int lane = threadIdx.x & 31, wid = threadIdx.x >> 5;
    int d = (i < N_NODES) ? g_deg[i] : 0;
    int incl = d;
#pragma unroll
    for (int off = 1; off < 32; off <<= 1) {
        int u = __shfl_up_sync(0xFFFFFFFFu, incl, off);
        if (lane >= off) incl += u;
    }
    __shared__ int wsum[SCAN_BLK / 32];
    __shared__ int wexcl[SCAN_BLK / 32];
    if (lane == 31) wsum[wid] = incl;
    __syncthreads();
    if (threadIdx.x == 0) {
        int run = 0;
#pragma unroll
        for (int w = 0; w < SCAN_BLK / 32; w++) { wexcl[w] = run; run += wsum[w]; }
    }
    __syncthreads();
    if (i < N_NODES) {
        int ex = incl - d + wexcl[wid] + g_boff[blockIdx.x];
        g_rowptr[i] = ex;
        g_cursor[i] = ex;
        g_invdeg[i] = (d > 0) ? (1.0f / (float)d) : 0.0f;
    }
}

__global__ void fill_kernel(const void* __restrict__ ei) {
    int e = blockIdx.x * blockDim.x + threadIdx.x;
    if (e >= N_EDGES) return;
    int is64 = g_is64;
    int s = load_edge(ei, e, is64);
    int d = load_edge(ei, N_EDGES + e, is64);
    int pos = atomicAdd(&g_cursor[d], 1);
    g_csr[pos] = s;
}

// ---------------- fused weight split + x conversion ----------------
#define WCONV_N (3 * 2 * 128 * 128)               // 98304 weight elements
#define XCONV_N (N_NODES * CH / 2)                // 3.2M x-pairs
__global__ void conv_kernel(const float* __restrict__ Wl0, const float* __restrict__ Wr0,
                            const float* __restrict__ Wl1, const float* __restrict__ Wr1,
                            const float* __restrict__ Wl2, const float* __restrict__ Wr2,
                            const float* __restrict__ x) {
    int id = blockIdx.x * blockDim.x + threadIdx.x;
    if (id < WCONV_N) {
        const float* W[3][2] = {{Wl0, Wr0}, {Wl1, Wr1}, {Wl2, Wr2}};
        int l = id / 32768;
        int rem = id % 32768;
        int mat = rem / 16384;
        int e = rem % 16384;
        float w = W[l][mat][e];
        __half hi = __float2half_rn(w);
        __half lo = __float2half_rn(w - __half2float(hi));
        g_wS[l][mat * 2 + 0][e] = hi;
        g_wS[l][mat * 2 + 1][e] = lo;
    }
    int xi = id - WCONV_N;
    if (xi >= 0 && xi < XCONV_N) {
        float2 v = ((const float2*)x)[xi];
        ((uint32_t*)g_xH)[xi] = h2pack(v.x, v.y);
    }
}

// ---------------- aggregation: one warp per node, coalesced idx + MLP8 ----------------
__global__ void agg_kernel(const __half* __restrict__ H) {
    int gt = blockIdx.x * blockDim.x + threadIdx.x;
    int node = gt >> 5;
    int lane = gt & 31;
    if (node >= N_NODES) return;
    int beg = g_rowptr[node];
    int n = g_rowptr[node + 1] - beg;

    float4 acc[8];
#pragma unroll
    for (int q = 0; q < 8; q++) acc[q] = make_float4(0.f, 0.f, 0.f, 0.f);

    const size_t laneoff = (size_t)(lane * 4);
    for (int base = 0; base < n; base += 32) {
        int cnt = n - base;
        if (cnt > 32) cnt = 32;
        // coalesced index fetch: one LDG per 32 edges
        int myidx = (lane < cnt) ? g_csr[beg + base + lane] : 0;
        int j = 0;
        for (; j + 8 <= cnt; j += 8) {
            int s0 = __shfl_sync(0xFFFFFFFFu, myidx, j + 0);
            int s1 = __shfl_sync(0xFFFFFFFFu, myidx, j + 1);
            int s2 = __shfl_sync(0xFFFFFFFFu, myidx, j + 2);
            int s3 = __shfl_sync(0xFFFFFFFFu, myidx, j + 3);
            int s4 = __shfl_sync(0xFFFFFFFFu, myidx, j + 4);
            int s5 = __shfl_sync(0xFFFFFFFFu, myidx, j + 5);
            int s6 = __shfl_sync(0xFFFFFFFFu, myidx, j + 6);
            int s7 = __shfl_sync(0xFFFFFFFFu, myidx, j + 7);
            uint2 r0 = *(const uint2*)(H + (size_t)s0 * CH + laneoff);
            uint2 r1 = *(const uint2*)(H + (size_t)s1 * CH + laneoff);
            uint2 r2 = *(const uint2*)(H + (size_t)s2 * CH + laneoff);
            uint2 r3 = *(const uint2*)(H + (size_t)s3 * CH + laneoff);
            uint2 r4 = *(const uint2*)(H + (size_t)s4 * CH + laneoff);
            uint2 r5 = *(const uint2*)(H + (size_t)s5 * CH + laneoff);
            uint2 r6 = *(const uint2*)(H + (size_t)s6 * CH + laneoff);
            uint2 r7 = *(const uint2*)(H + (size_t)s7 * CH + laneoff);
#define ACC(q, r) do { float2 _a = h2unpack(r.x), _b = h2unpack(r.y); \
            acc[q].x += _a.x; acc[q].y += _a.y; acc[q].z += _b.x; acc[q].w += _b.y; } while (0)
            ACC(0, r0); ACC(1, r1); ACC(2, r2); ACC(3, r3);
            ACC(4, r4); ACC(5, r5); ACC(6, r6); ACC(7, r7);
        }
        for (; j < cnt; j++) {
            int s0 = __shfl_sync(0xFFFFFFFFu, myidx, j);
            uint2 r0 = *(const uint2*)(H + (size_t)s0 * CH + laneoff);
            ACC(0, r0);
#undef ACC
        }
    }
#pragma unroll
    for (int q = 1; q < 8; q++) {
        acc[0].x += acc[q].x; acc[0].y += acc[q].y;
        acc[0].z += acc[q].z; acc[0].w += acc[q].w;
    }
    float s = g_invdeg[node];
    uint2 p;
    p.x = h2pack(acc[0].x * s, acc[0].y * s);
    p.y = h2pack(acc[0].z * s, acc[0].w * s);
    *(uint2*)(g_aggH + (size_t)node * CH + laneoff) = p;
}

// ---------------- tensor-core fused dual GEMM via mma.sync (fp16) ----------------
// Out = relu(Agg@Wl + bl + H@Wr); weights split exact: x*(wh+wl), 2 products.
// CTA: 128x128 tile; 8 warps (4M x 2N), warp tile m32 x n64; K chunk 64.
#define SM_A 0                 // 2 arrays x [128][64] fp16 = 32 KB
#define SM_W 32768             // 4 mats   x [64][128] fp16 = 64 KB
#define TC_SMEM 98304

__global__ void __launch_bounds__(256, 2)
tc_gemm_kernel(const __half* __restrict__ aggH, const __half* __restrict__ hH,
               const __half* __restrict__ WS,  // [4][128*128] k-major: WlH,WlL,WrH,WrL
               const float* __restrict__ bl, __half* __restrict__ hHOut) {
    extern __shared__ char smem[];
    uint32_t sb = smem_u32(smem);
    int tid = threadIdx.x;
    int lane = tid & 31;
    int warp = tid >> 5;
    int warpM = warp & 3;         // 0..3 -> m offset *32
    int warpN = warp >> 2;        // 0..1 -> n offset *64
    int row0 = blockIdx.x * 128;
    int mwbase = warpM * 32;
    int n0 = warpN * 64;

    const __half* Asrc[2] = {aggH, hH};

    float acc[2][8][4];
#pragma unroll
    for (int mi = 0; mi < 2; mi++)
#pragma unroll
        for (int j = 0; j < 8; j++)
#pragma unroll
            for (int q = 0; q < 4; q++) acc[mi][j][q] = 0.f;

    for (int kc = 0; kc < 128; kc += 64) {
        __syncthreads();
        // stage A: 2 arrays x 128 rows x 8 units(16B)
        for (int idx = tid; idx < 2048; idx += 256) {
            int arr = idx >> 10;
            int rem = idx & 1023;
            int r = rem >> 3;
            int u = rem & 7;
            int row = row0 + r;
            uint4 v = make_uint4(0u, 0u, 0u, 0u);
            if (row < N_NODES)
                v = *(const uint4*)(Asrc[arr] + (size_t)row * CH + kc + u * 8);
            uint32_t b = (uint32_t)(r * 128 + u * 16) ^ (uint32_t)((r & 7) << 4);
            *(uint4*)(smem + SM_A + arr * 16384 + b) = v;
        }
        // stage W: 4 mats x 64 k-rows x 16 units
        for (int idx = tid; idx < 4096; idx += 256) {
            int mat = idx >> 10;
            int rem = idx & 1023;
            int k = rem >> 4;
            int u = rem & 15;
            uint4 v = *(const uint4*)(WS + mat * 16384 + (kc + k) * 128 + u * 8);
            uint32_t b = (uint32_t)(k * 256 + u * 16) ^ (uint32_t)((k & 7) << 4);
            *(uint4*)(smem + SM_W + mat * 16384 + b) = v;
        }
        __syncthreads();

#pragma unroll
        for (int k16 = 0; k16 < 4; k16++) {
            int k0 = k16 * 16;
#pragma unroll
            for (int grp = 0; grp < 2; grp++) {   // 0: agg x Wl, 1: h x Wr
                uint32_t a[2][4];
                ldmA(a[0], sb + SM_A + grp * 16384, mwbase, k0, lane);
                ldmA(a[1], sb + SM_A + grp * 16384, mwbase + 16, k0, lane);
#pragma unroll
                for (int j = 0; j < 4; j++) {
                    uint32_t bh[4], blo[4];
                    ldmB(bh,  sb + SM_W + (grp * 2 + 0) * 16384, k0, n0 + j * 16, lane);
                    ldmB(blo, sb + SM_W + (grp * 2 + 1) * 16384, k0, n0 + j * 16, lane);
#pragma unroll
                    for (int mi = 0; mi < 2; mi++) {
                        MMA_F16(acc[mi][2 * j],     a[mi], bh[0],  bh[1]);
                        MMA_F16(acc[mi][2 * j + 1], a[mi], bh[2],  bh[3]);
                        MMA_F16(acc[mi][2 * j],     a[mi], blo[0], blo[1]);
                        MMA_F16(acc[mi][2 * j + 1], a[mi], blo[2], blo[3]);
                    }
                }
            }
        }
    }

    // ---- epilogue: bias + relu -> fp16 ----
    int g = lane >> 2, tg = lane & 3;
#pragma unroll
    for (int mi = 0; mi < 2; mi++) {
        int r1 = row0 + mwbase + mi * 16 + g;
#pragma unroll
        for (int j = 0; j < 8; j++) {
            int col = n0 + j * 8 + tg * 2;
            float2 bb = *(const float2*)(bl + col);
            float o0 = fmaxf(acc[mi][j][0] + bb.x, 0.f);
            float o1 = fmaxf(acc[mi][j][1] + bb.y, 0.f);
            float o2 = fmaxf(acc[mi][j][2] + bb.x, 0.f);
            float o3 = fmaxf(acc[mi][j][3] + bb.y, 0.f);
            if (r1 < N_NODES)
                *(uint32_t*)(hHOut + (size_t)r1 * CH + col) = h2pack(o0, o1);
            if (r1 + 8 < N_NODES)
                *(uint32_t*)(hHOut + (size_t)(r1 + 8) * CH + col) = h2pack(o2, o3);
        }
    }
}

// ---------------- head: logits = H @ Wh + bh, one warp per node (fp16 H) ----------------
__global__ void head_kernel(const __half* __restrict__ H, const float* __restrict__ Wh,
                            const float* __restrict__ bh, float* __restrict__ out) {
    __shared__ float sWh[CH];
    if (threadIdx.x < CH) sWh[threadIdx.x] = Wh[threadIdx.x];
    __syncthreads();
    int gt = blockIdx.x * blockDim.x + threadIdx.x;
    int node = gt >> 5;
    int lane = gt & 31;
    if (node >= N_NODES) return;
    uint2 r = *(const uint2*)(H + (size_t)node * CH + lane * 4);
    float2 a = h2unpack(r.x), b = h2unpack(r.y);
    float4 w = *(const float4*)(sWh + lane * 4);
    float s = a.x * w.x + a.y * w.y + b.x * w.z + b.y * w.w;
#pragma unroll
    for (int off = 16; off > 0; off >>= 1)
        s += __shfl_down_sync(0xFFFFFFFFu, s, off);
    if (lane == 0) out[node] = s + bh[0];
}

// ---------------- launch ----------------
extern "C" void kernel_launch(void* const* d_in, const int* in_sizes, int n_in,
                              void* d_out, int out_size) {
    const float* x  = (const float*)d_in[0];
    const void*  ei = d_in[1];
    const float* Wl[3] = {(const float*)d_in[2], (const float*)d_in[5], (const float*)d_in[8]};
    const float* Wr[3] = {(const float*)d_in[3], (const float*)d_in[6], (const float*)d_in[9]};
    const float* bl[3] = {(const float*)d_in[4], (const float*)d_in[7], (const float*)d_in[10]};
    const float* Wh = (const float*)d_in[11];
    const float* bh = (const float*)d_in[12];
    float* out = (float*)d_out;

    cudaFuncSetAttribute(tc_gemm_kernel, cudaFuncAttributeMaxDynamicSharedMemorySize,
                         TC_SMEM);

    void *pW, *pXH, *pAH, *pHA, *pHB;
    cudaGetSymbolAddress(&pW, g_wS);
    cudaGetSymbolAddress(&pXH, g_xH);
    cudaGetSymbolAddress(&pAH, g_aggH);
    cudaGetSymbolAddress(&pHA, g_hHA);
    cudaGetSymbolAddress(&pHB, g_hHB);
    const __half* wS = (const __half*)pW;

    // CSR build + weight/x conversion
    zero_detect_kernel<<<(N_NODES + 255) / 256, 256>>>((const unsigned*)ei);
    deg_kernel<<<(N_EDGES + 255) / 256, 256>>>(ei);
    bsum_kernel<<<NSCAN_BLOCKS, SCAN_BLK>>>();
    bscan_kernel<<<1, 128>>>();
    scatter_scan_kernel<<<NSCAN_BLOCKS, SCAN_BLK>>>();
    fill_kernel<<<(N_EDGES + 255) / 256, 256>>>(ei);
    conv_kernel<<<(WCONV_N + XCONV_N + 255) / 256, 256>>>(
        Wl[0], Wr[0], Wl[1], Wr[1], Wl[2], Wr[2], x);

    const int warp_grid = (N_NODES * 32 + 255) / 256;
    const int gemm_grid = (N_NODES + 127) / 128;  // 391

    const __half* hH_in[3] = {(__half*)pXH, (__half*)pHA, (__half*)pHB};
    __half* hH_out[3] = {(__half*)pHA, (__half*)pHB, (__half*)pHA};

    for (int l = 0; l < 3; l++) {
        agg_kernel<<<warp_grid, 256>>>(hH_in[l]);
        tc_gemm_kernel<<<gemm_grid, 256, TC_SMEM>>>(
            (__half*)pAH, hH_in[l], wS + (size_t)l * 4 * 16384, bl[l], hH_out[l]);
    }
    head_kernel<<<warp_grid, 256>>>(hH_out[2], Wh, bh, out);
}